// round 12
// baseline (speedup 1.0000x reference)
#include <cuda_runtime.h>
#include <cuda_fp16.h>
#include <math.h>
#include <stdint.h>

#define NN 1024
#define BB 64
#define NB 65536
#define HH 128
#define F0R 130
#define FP0 160                  // layer0 padded features, [s(128), inp(2), 0...]
#define FP1 256
#define BF0 (BB*FP0)             // 10240
#define BF1 (BB*FP1)             // 16384
#define K50 (5*FP0)              // 800
#define K51 (5*FP1)              // 1280
#define PITCH 40                 // halves per smem row (80B, 16B-aligned, conflict-free)
#define SMEM_SZ 122880           // 2 stages x (2*BM+2*BN=768 rows) x PITCH x 2B

// ---------------- static device scratch ----------------
__device__ __align__(128) __half g_Ah[(size_t)NB*K51];
__device__ __align__(128) __half g_Al[(size_t)NB*K51];
__device__ __align__(128) __half g_Xth[(size_t)BF1*NN];
__device__ __align__(128) __half g_Xtl[(size_t)BF1*NN];
__device__ __align__(128) __half g_Gh[(size_t)4096*NN];
__device__ __align__(128) __half g_Gl[(size_t)4096*NN];
__device__ __align__(128) float  g_sq[(size_t)2*NN*NN];
__device__ __align__(128) __half g_Wg0h[256*K50], g_Wg0l[256*K50];
__device__ __align__(128) __half g_Wc0h[128*K50], g_Wc0l[128*K50];
__device__ __align__(128) __half g_Wg1h[256*K51], g_Wg1l[256*K51];
__device__ __align__(128) __half g_Wc1h[128*K51], g_Wc1l[128*K51];
__device__ __align__(128) float  g_gate[(size_t)NB*256];
__device__ __align__(128) float  g_s0[(size_t)NB*HH];
__device__ __align__(128) float  g_s1[(size_t)NB*HH];

// ---------------- helpers ----------------
__device__ __forceinline__ uint32_t smem_u32(const void* p){
    uint32_t a; asm("{ .reg .u64 t; cvta.to.shared.u64 t, %1; cvt.u32.u64 %0, t; }":"=r"(a):"l"(p)); return a;
}
__device__ __forceinline__ void cp16(uint32_t d, const void* s){
    asm volatile("cp.async.cg.shared.global [%0], [%1], 16;\n"::"r"(d),"l"(s):"memory");
}
__device__ __forceinline__ void ldmA(uint32_t* a, uint32_t addr){
    asm volatile("ldmatrix.sync.aligned.m8n8.x4.shared.b16 {%0,%1,%2,%3}, [%4];"
        : "=r"(a[0]),"=r"(a[1]),"=r"(a[2]),"=r"(a[3]) : "r"(addr));
}
__device__ __forceinline__ void ldmB4(uint32_t& b0, uint32_t& b1, uint32_t& b2, uint32_t& b3, uint32_t addr){
    asm volatile("ldmatrix.sync.aligned.m8n8.x4.shared.b16 {%0,%1,%2,%3}, [%4];"
        : "=r"(b0),"=r"(b1),"=r"(b2),"=r"(b3) : "r"(addr));
}
__device__ __forceinline__ void mma16816(float* d, const uint32_t* a, const uint32_t* b){
    asm volatile("mma.sync.aligned.m16n8k16.row.col.f32.f16.f16.f32 "
        "{%0,%1,%2,%3},{%4,%5,%6,%7},{%8,%9},{%0,%1,%2,%3};"
        : "+f"(d[0]),"+f"(d[1]),"+f"(d[2]),"+f"(d[3])
        : "r"(a[0]),"r"(a[1]),"r"(a[2]),"r"(a[3]),"r"(b[0]),"r"(b[1]));
}

// ---------------- fp16-split HGEMM: quad-tile, 3 products, templated tiles ----------------
// Block tile (2*WM) x (4*WN), BK=32. acc = Ah@Bh^T + Ah@Bl^T + Al@Bh^T; A,B K-major.
// mode 0: split-write Y into g_Ah/g_Al; B rows are (b*fCnt + j), feature f = fLo + j
// mode 1: gate[row*256+c] = sigmoid(v + bias[c])
// mode 2: state[row*128+c] = u*s + (1-u)*tanh(v + bias[c])
struct GArgs {
    const __half *Ah,*Al,*Bh,*Bl;
    int lda, ldb, nch, mode, fp, k5, fLo, fCnt;
    const float* bias; float* gate; float* state;
};

template<int WM, int WN>
__global__ __launch_bounds__(256,1) void hgemm(GArgs g)
{
    constexpr int BM = 2*WM, BN = 4*WN;
    constexpr int MI = WM/16, NI = WN/8;
    constexpr int SH = (2*BM + 2*BN) * PITCH;   // halves per stage
    extern __shared__ __align__(16) __half sm[];
    const int tid = threadIdx.x;
    const int wid = tid >> 5, lane = tid & 31;
    const int m0 = blockIdx.y * BM, n0 = blockIdx.x * BN;
    const int mbase = (wid >> 2) * WM, nbase = (wid & 3) * WN;
    const uint32_t smb = smem_u32(sm);

    float acc[MI][NI][4];
#pragma unroll
    for (int i = 0; i < MI; i++)
#pragma unroll
        for (int j = 0; j < NI; j++)
#pragma unroll
            for (int k = 0; k < 4; k++) acc[i][j][k] = 0.f;

    auto fill = [&](int c, int buf){
        const int k0 = c * 32;
        const __half* A0 = g.Ah + (size_t)m0 * g.lda + k0;
        const __half* A1 = g.Al + (size_t)m0 * g.lda + k0;
        const __half* B0 = g.Bh + (size_t)n0 * g.ldb + k0;
        const __half* B1 = g.Bl + (size_t)n0 * g.ldb + k0;
        const uint32_t sb = smb + buf * SH * 2;
#pragma unroll
        for (int i = tid; i < BM*4; i += 256) {
            const int r = i >> 2, cc = (i & 3) * 8;
            const uint32_t d = sb + (r*PITCH + cc)*2;
            cp16(d, A0 + (size_t)r * g.lda + cc);
            cp16(d + BM*PITCH*2, A1 + (size_t)r * g.lda + cc);
        }
#pragma unroll
        for (int i = tid; i < BN*4; i += 256) {
            const int r = i >> 2, cc = (i & 3) * 8;
            const uint32_t d = sb + (2*BM*PITCH + r*PITCH + cc)*2;
            cp16(d, B0 + (size_t)r * g.ldb + cc);
            cp16(d + BN*PITCH*2, B1 + (size_t)r * g.ldb + cc);
        }
        asm volatile("cp.async.commit_group;\n":::"memory");
    };

    fill(0, 0);
    for (int c = 0; c < g.nch; c++) {
        const int buf = c & 1;
        if (c + 1 < g.nch) {
            fill(c + 1, buf ^ 1);
            asm volatile("cp.async.wait_group 1;\n":::"memory");
        } else {
            asm volatile("cp.async.wait_group 0;\n":::"memory");
        }
        __syncthreads();
        const uint32_t sb = smb + buf * SH * 2;
        const uint32_t aH = sb, aL = sb + BM*PITCH*2;
        const uint32_t bH = sb + 2*BM*PITCH*2, bL = bH + BN*PITCH*2;
        const int g8 = lane >> 3, l8 = lane & 7;
#pragma unroll
        for (int ks = 0; ks < 2; ks++) {
            const int chA = ks*16 + (lane >> 4) * 8;
            const int chB = ks*16 + (g8 & 1) * 8;
            uint32_t afr[MI][4], bfr[NI][2];
            // product 1: Ah @ Bl
#pragma unroll
            for (int mi = 0; mi < MI; mi++) {
                const int r = mbase + mi*16 + (lane & 15);
                ldmA(afr[mi], aH + (r*PITCH + chA)*2);
            }
#pragma unroll
            for (int ni2 = 0; ni2 < NI/2; ni2++) {
                const int r = nbase + ni2*16 + (g8 >> 1) * 8 + l8;
                ldmB4(bfr[2*ni2][0], bfr[2*ni2][1], bfr[2*ni2+1][0], bfr[2*ni2+1][1],
                      bL + (r*PITCH + chB)*2);
            }
#pragma unroll
            for (int mi = 0; mi < MI; mi++)
#pragma unroll
                for (int ni = 0; ni < NI; ni++)
                    mma16816(acc[mi][ni], afr[mi], bfr[ni]);
            // product 2: Ah @ Bh (reuse afr)
#pragma unroll
            for (int ni2 = 0; ni2 < NI/2; ni2++) {
                const int r = nbase + ni2*16 + (g8 >> 1) * 8 + l8;
                ldmB4(bfr[2*ni2][0], bfr[2*ni2][1], bfr[2*ni2+1][0], bfr[2*ni2+1][1],
                      bH + (r*PITCH + chB)*2);
            }
#pragma unroll
            for (int mi = 0; mi < MI; mi++)
#pragma unroll
                for (int ni = 0; ni < NI; ni++)
                    mma16816(acc[mi][ni], afr[mi], bfr[ni]);
            // product 3: Al @ Bh (reuse bfr)
#pragma unroll
            for (int mi = 0; mi < MI; mi++) {
                const int r = mbase + mi*16 + (lane & 15);
                ldmA(afr[mi], aL + (r*PITCH + chA)*2);
            }
#pragma unroll
            for (int mi = 0; mi < MI; mi++)
#pragma unroll
                for (int ni = 0; ni < NI; ni++)
                    mma16816(acc[mi][ni], afr[mi], bfr[ni]);
        }
        __syncthreads();
    }

    // ---------------- epilogue ----------------
#pragma unroll
    for (int mi = 0; mi < MI; mi++) {
#pragma unroll
        for (int h2 = 0; h2 < 2; h2++) {
            const int rg = m0 + mbase + mi*16 + (lane >> 2) + h2*8;
#pragma unroll
            for (int ni = 0; ni < NI; ni++) {
                const int cg = n0 + nbase + ni*8 + (lane & 3)*2;
                const float v0 = acc[mi][ni][h2*2 + 0];
                const float v1 = acc[mi][ni][h2*2 + 1];
                if (g.mode == 0) {
                    const int s = rg >> 10, n = rg & 1023;
                    const int b = cg / g.fCnt;
                    const int f = g.fLo + (cg - b * g.fCnt);
                    const size_t base = (size_t)(n*64 + b) * g.k5 + (size_t)(s+1) * g.fp + f;
                    const __half h0 = __float2half_rn(v0), h1 = __float2half_rn(v1);
                    __half2 hh; hh.x = h0; hh.y = h1;
                    __half2 ll;
                    ll.x = __float2half_rn(v0 - __half2float(h0));
                    ll.y = __float2half_rn(v1 - __half2float(h1));
                    *(__half2*)(g_Ah + base) = hh;
                    *(__half2*)(g_Al + base) = ll;
                } else if (g.mode == 1) {
                    float2 o;
                    o.x = 1.f/(1.f + expf(-(v0 + g.bias[cg+0])));
                    o.y = 1.f/(1.f + expf(-(v1 + g.bias[cg+1])));
                    *(float2*)(g.gate + (size_t)rg*256 + cg) = o;
                } else {
                    const float2 u = *(const float2*)(g.gate + (size_t)rg*256 + 128 + cg);
                    const float2 so = *(const float2*)(g.state + (size_t)rg*128 + cg);
                    float2 o;
                    o.x = u.x*so.x + (1.f-u.x)*tanhf(v0 + g.bias[cg+0]);
                    o.y = u.y*so.y + (1.f-u.y)*tanhf(v1 + g.bias[cg+1]);
                    *(float2*)(g.state + (size_t)rg*128 + cg) = o;
                }
            }
        }
    }
}

// ---------------- fp32 SGEMM for prologue: C = 2 * A @ A (1024^3) ----------------
__global__ __launch_bounds__(256)
void sgemm_sq(const float* __restrict__ A, float* __restrict__ C)
{
    __shared__ float As[2][8][128];
    __shared__ float Bs[2][8][128];
    const int tid = threadIdx.x;
    const int m0 = blockIdx.y * 128, n0 = blockIdx.x * 128;
    const int arow = tid >> 1, acol = (tid & 1) << 2;
    const int brow = tid >> 5, bcol = (tid & 31) << 2;
    const float* Ap = A + (size_t)(m0 + arow) * NN + acol;
    const float* Bp = A + (size_t)brow * NN + n0 + bcol;
    const int tx = tid & 15, ty = tid >> 4;
    float acc[8][8];
#pragma unroll
    for (int i = 0; i < 8; i++)
#pragma unroll
        for (int j = 0; j < 8; j++) acc[i][j] = 0.f;
    float4 a4 = *(const float4*)Ap, b4 = *(const float4*)Bp;
    As[0][acol+0][arow]=a4.x; As[0][acol+1][arow]=a4.y; As[0][acol+2][arow]=a4.z; As[0][acol+3][arow]=a4.w;
    *(float4*)(&Bs[0][brow][bcol]) = b4;
    __syncthreads();
    for (int it = 0; it < 128; ++it) {
        const int buf = it & 1;
        if (it + 1 < 128) {
            const int k0 = (it + 1) << 3;
            a4 = *(const float4*)(Ap + k0);
            b4 = *(const float4*)(Bp + (size_t)k0 * NN);
        }
#pragma unroll
        for (int kk = 0; kk < 8; ++kk) {
            float ar[8], br[8];
            *(float4*)&ar[0] = *(const float4*)&As[buf][kk][ty*8];
            *(float4*)&ar[4] = *(const float4*)&As[buf][kk][ty*8+4];
            *(float4*)&br[0] = *(const float4*)&Bs[buf][kk][tx*8];
            *(float4*)&br[4] = *(const float4*)&Bs[buf][kk][tx*8+4];
#pragma unroll
            for (int i = 0; i < 8; i++)
#pragma unroll
                for (int j = 0; j < 8; j++) acc[i][j] = fmaf(ar[i], br[j], acc[i][j]);
        }
        if (it + 1 < 128) {
            const int nb2 = buf ^ 1;
            As[nb2][acol+0][arow]=a4.x; As[nb2][acol+1][arow]=a4.y; As[nb2][acol+2][arow]=a4.z; As[nb2][acol+3][arow]=a4.w;
            *(float4*)(&Bs[nb2][brow][bcol]) = b4;
            __syncthreads();
        }
    }
#pragma unroll
    for (int i = 0; i < 8; i++) {
        float* Cp = C + (size_t)(m0 + ty*8 + i) * NN + n0 + tx*8;
#pragma unroll
        for (int j = 0; j < 8; j++) Cp[j] = 2.f * acc[i][j];
    }
}

// ---------------- builders ----------------
// layer0 feature order: [s(128), inp(2), pad(30)]
__device__ __forceinline__ float xval0(const float* __restrict__ inp, int n, int b, int f, int reset){
    if (f < 128) {
        float s = g_s0[((size_t)n*64 + b)*HH + f];
        if (reset) s *= g_gate[((size_t)n*64 + b)*256 + f];
        return s;
    }
    if (f < 130) return inp[((size_t)b*NN + n)*2 + (f - 128)];
    return 0.f;
}
// layer1 feature order: [s0(128), s1(128)]
__device__ __forceinline__ float xval1(int n, int b, int f, int reset){
    if (f < HH) return g_s0[((size_t)n*64 + b)*HH + f];
    const int j = f - HH;
    float s = g_s1[((size_t)n*64 + b)*HH + j];
    if (reset) s *= g_gate[((size_t)n*64 + b)*256 + j];
    return s;
}

__global__ void build_a(const float* __restrict__ inp, int layer, int reset, int fp, int k5){
    const int row = blockIdx.x, f = threadIdx.x;
    const int n = row >> 6, b = row & 63;
    const float v = layer ? xval1(n, b, f, reset) : xval0(inp, n, b, f, reset);
    __half h = __float2half_rn(v);
    g_Ah[(size_t)row*k5 + f] = h;
    g_Al[(size_t)row*k5 + f] = __float2half_rn(v - __half2float(h));
}

// writes Xt rows (b*fCnt + j)*NN + n for features f = fLo + j, j in [0, fCnt)
__global__ void build_xt(const float* __restrict__ inp, int layer, int reset, int fLo, int fCnt){
    __shared__ float t[32][33];
    const int b = blockIdx.z, j0 = blockIdx.y*32, nt = blockIdx.x*32;
    const int tx = threadIdx.x, ty = threadIdx.y;
#pragma unroll
    for (int k = 0; k < 4; k++) {
        const int n = nt + ty + 8*k, f = fLo + j0 + tx;
        t[ty + 8*k][tx] = layer ? xval1(n, b, f, reset) : xval0(inp, n, b, f, reset);
    }
    __syncthreads();
#pragma unroll
    for (int k = 0; k < 4; k++) {
        const int j = j0 + ty + 8*k, n = nt + tx;
        const float v = t[tx][ty + 8*k];
        __half h = __float2half_rn(v);
        const size_t o = ((size_t)b*fCnt + j)*NN + n;
        g_Xth[o] = h;
        g_Xtl[o] = __float2half_rn(v - __half2float(h));
    }
}

__global__ void split_G(const float* __restrict__ sup){
    size_t i = (size_t)blockIdx.x * blockDim.x + threadIdx.x;
    if (i >= (size_t)4096*NN) return;
    const int row = (int)(i >> 10), col = (int)(i & 1023);
    const int slice = row >> 10, n = row & 1023;
    float v;
    if (slice == 0)      v = sup[(size_t)n*NN + col];
    else if (slice == 1) v = g_sq[(size_t)n*NN + col];
    else if (slice == 2) v = sup[(size_t)NN*NN + (size_t)n*NN + col];
    else                 v = g_sq[(size_t)NN*NN + (size_t)n*NN + col];
    __half h = __float2half_rn(v);
    g_Gh[i] = h;
    g_Gl[i] = __float2half_rn(v - __half2float(h));
}

// swapInp: layer0 reorder — W row for new f: f<128 -> orig 2+f; f in [128,130) -> orig f-128; else 0
__global__ void build_wt(__half* __restrict__ Wh, __half* __restrict__ Wl,
                         const float* __restrict__ src, int O, int F, int fp, int swapInp){
    const int k5 = 5*fp;
    int i = blockIdx.x * blockDim.x + threadIdx.x;
    if (i >= O*k5) return;
    const int o = i / k5, k = i - o*k5;
    const int t = k / fp, f = k - t*fp;
    int fo = f;
    if (swapInp) fo = (f < 128) ? (f + 2) : ((f < 130) ? (f - 128) : F);
    float v = 0.f;
    if (fo < F) {
        #define WSK(s,kx) src[((((size_t)(s))*3 + (kx))*F + fo)*O + o]
        switch (t) {
            case 0: v = WSK(0,0)+WSK(1,0)-WSK(0,2)-WSK(1,2); break;
            case 1: v = WSK(0,1); break;
            case 2: v = WSK(0,2); break;
            case 3: v = WSK(1,1); break;
            case 4: v = WSK(1,2); break;
        }
        #undef WSK
    }
    __half h = __float2half_rn(v);
    Wh[i] = h;
    Wl[i] = __float2half_rn(v - __half2float(h));
}

__global__ void write_out(float* __restrict__ out){
    const int nb = blockIdx.x, h = threadIdx.x;
    const int n = nb >> 6, b = nb & 63;
    out[(((size_t)0*BB + b)*NN + n)*HH + h] = g_s0[(size_t)nb*HH + h];
    out[(((size_t)1*BB + b)*NN + n)*HH + h] = g_s1[(size_t)nb*HH + h];
}

// ---------------- host ----------------
static void run_g(dim3 grid, const __half* Ah, const __half* Al,
                  const __half* Bh, const __half* Bl,
                  int lda, int ldb, int nch, int mode, int fp, int k5,
                  int fLo, int fCnt,
                  const float* bias, float* gate, float* state)
{
    GArgs g{Ah,Al,Bh,Bl,lda,ldb,nch,mode,fp,k5,fLo,fCnt,bias,gate,state};
    hgemm<64,64><<<grid, 256, SMEM_SZ>>>(g);
}
static void run_c(dim3 grid, const __half* Ah, const __half* Al,
                  const __half* Bh, const __half* Bl,
                  int lda, int ldb, int nch, int mode, int fp, int k5,
                  const float* bias, float* gate, float* state)
{
    GArgs g{Ah,Al,Bh,Bl,lda,ldb,nch,mode,fp,k5,0,0,bias,gate,state};
    hgemm<128,32><<<grid, 256, SMEM_SZ>>>(g);
}

extern "C" void kernel_launch(void* const* d_in, const int* in_sizes, int n_in,
                              void* d_out, int out_size)
{
    const float* inputs = (const float*)d_in[0];
    const float* sup    = (const float*)d_in[1];
    const float* ruW0 = (const float*)d_in[2];
    const float* rub0 = (const float*)d_in[3];
    const float* hW0  = (const float*)d_in[4];
    const float* hb0  = (const float*)d_in[5];
    const float* ruW1 = (const float*)d_in[6];
    const float* rub1 = (const float*)d_in[7];
    const float* hW1  = (const float*)d_in[8];
    const float* hb1  = (const float*)d_in[9];
    float* out = (float*)d_out;

    cudaFuncSetAttribute(hgemm<64,64>,  cudaFuncAttributeMaxDynamicSharedMemorySize, SMEM_SZ);
    cudaFuncSetAttribute(hgemm<128,32>, cudaFuncAttributeMaxDynamicSharedMemorySize, SMEM_SZ);

    float *SQ, *S0, *S1, *GATE;
    __half *Ah, *Al, *Xth, *Xtl, *Gh, *Gl;
    __half *Wg0h,*Wg0l,*Wc0h,*Wc0l,*Wg1h,*Wg1l,*Wc1h,*Wc1l;
    cudaGetSymbolAddress((void**)&SQ, g_sq);
    cudaGetSymbolAddress((void**)&S0, g_s0);
    cudaGetSymbolAddress((void**)&S1, g_s1);
    cudaGetSymbolAddress((void**)&GATE, g_gate);
    cudaGetSymbolAddress((void**)&Ah, g_Ah);
    cudaGetSymbolAddress((void**)&Al, g_Al);
    cudaGetSymbolAddress((void**)&Xth, g_Xth);
    cudaGetSymbolAddress((void**)&Xtl, g_Xtl);
    cudaGetSymbolAddress((void**)&Gh, g_Gh);
    cudaGetSymbolAddress((void**)&Gl, g_Gl);
    cudaGetSymbolAddress((void**)&Wg0h, g_Wg0h); cudaGetSymbolAddress((void**)&Wg0l, g_Wg0l);
    cudaGetSymbolAddress((void**)&Wc0h, g_Wc0h); cudaGetSymbolAddress((void**)&Wc0l, g_Wc0l);
    cudaGetSymbolAddress((void**)&Wg1h, g_Wg1h); cudaGetSymbolAddress((void**)&Wg1l, g_Wg1l);
    cudaGetSymbolAddress((void**)&Wc1h, g_Wc1h); cudaGetSymbolAddress((void**)&Wc1l, g_Wc1l);

    // prologue
    sgemm_sq<<<dim3(8,8), 256>>>(sup, SQ);
    sgemm_sq<<<dim3(8,8), 256>>>(sup + (size_t)NN*NN, SQ + (size_t)NN*NN);
    split_G<<<(4096*1024)/256, 256>>>(sup);
    build_wt<<<(256*K50+255)/256, 256>>>(Wg0h, Wg0l, ruW0, 256, F0R, FP0, 1);
    build_wt<<<(128*K50+255)/256, 256>>>(Wc0h, Wc0l, hW0, 128, F0R, FP0, 1);
    build_wt<<<(256*K51+255)/256, 256>>>(Wg1h, Wg1l, ruW1, 256, FP1, FP1, 0);
    build_wt<<<(128*K51+255)/256, 256>>>(Wc1h, Wc1l, hW1, 128, FP1, FP1, 0);
    cudaMemsetAsync(S0, 0, (size_t)NB*HH*4);
    cudaMemsetAsync(S1, 0, (size_t)NB*HH*4);

    const dim3 gg0(BF0/256, 32);        // (40, 32)  layer0 gate graph
    const dim3 gg1(BF1/256, 32);        // (64, 32)  layer1 gate graph
    const dim3 gcand(32, 32);           // candidate graph (128 feats x 64 batch = 8192 cols)
    const dim3 wgate(1, 512);           // weight gate: 128x256 tiles
    const dim3 wcand(1, 256);           // weight cand: 256x128 tiles
    const dim3 xtf0(32, FP0/32, BB), xtf1(32, FP1/32, BB), xtc(32, 4, BB);
    const dim3 bxt(32, 8);

    for (int t = 0; t < 12; ++t) {
        const float* inp = inputs + (size_t)t * BB * NN * 2;
        // ---- layer 0 gate: full X ----
        build_a<<<NB, FP0>>>(inp, 0, 0, FP0, K50);
        build_xt<<<xtf0, bxt>>>(inp, 0, 0, 0, FP0);
        run_g(gg0, Gh, Gl, Xth, Xtl, NN, NN, 32, 0, FP0, K50, 0, FP0, 0, 0, 0);
        run_g(wgate, Ah, Al, Wg0h, Wg0l, K50, K50, 25, 1, FP0, K50, 0, 0, rub0, GATE, 0);
        // ---- layer 0 candidate: only s-features (f 0..127) change ----
        build_a<<<NB, FP0>>>(inp, 0, 1, FP0, K50);
        build_xt<<<xtc, bxt>>>(inp, 0, 1, 0, 128);
        run_g(gcand, Gh, Gl, Xth, Xtl, NN, NN, 32, 0, FP0, K50, 0, 128, 0, 0, 0);
        run_c(wcand, Ah, Al, Wc0h, Wc0l, K50, K50, 25, 2, FP0, K50, hb0, GATE, S0);
        // ---- layer 1 gate: full X ----
        build_a<<<NB, FP1>>>(inp, 1, 0, FP1, K51);
        build_xt<<<xtf1, bxt>>>(inp, 1, 0, 0, FP1);
        run_g(gg1, Gh, Gl, Xth, Xtl, NN, NN, 32, 0, FP1, K51, 0, FP1, 0, 0, 0);
        run_g(wgate, Ah, Al, Wg1h, Wg1l, K51, K51, 40, 1, FP1, K51, 0, 0, rub1, GATE, 0);
        // ---- layer 1 candidate: only s1-features (f 128..255) change ----
        build_a<<<NB, FP1>>>(inp, 1, 1, FP1, K51);
        build_xt<<<xtc, bxt>>>(inp, 1, 1, 128, 128);
        run_g(gcand, Gh, Gl, Xth, Xtl, NN, NN, 32, 0, FP1, K51, 128, 128, 0, 0, 0);
        run_c(wcand, Ah, Al, Wc1h, Wc1l, K51, K51, 40, 2, FP1, K51, hb1, GATE, S1);
    }
    write_out<<<NB, 128>>>(out);
}

// round 14
// speedup vs baseline: 1.2027x; 1.2027x over previous
#include <cuda_runtime.h>
#include <cuda_fp16.h>
#include <math.h>
#include <stdint.h>

#define NN 1024
#define BB 64
#define NB 65536
#define HH 128
#define F0R 130
#define FP0 160                  // layer0 padded features, [s(128), inp(2), 0...]
#define FP1 256
#define BF0 (BB*FP0)             // 10240
#define BF1 (BB*FP1)             // 16384
#define K50 (5*FP0)              // 800
#define K51 (5*FP1)              // 1280
#define PITCH 40                 // halves per smem row (80B, 16B-aligned, conflict-free)
#define TSH (128*PITCH)
#define SMEM_SZ (2*4*TSH*2)      // 81920

// ---------------- static device scratch ----------------
__device__ __align__(128) __half g_Ah[(size_t)NB*K51];
__device__ __align__(128) __half g_Al[(size_t)NB*K51];
__device__ __align__(128) __half g_Xth[(size_t)BF1*NN];
__device__ __align__(128) __half g_Xtl[(size_t)BF1*NN];
__device__ __align__(128) __half g_Gh[(size_t)4096*NN];
__device__ __align__(128) __half g_Gl[(size_t)4096*NN];
__device__ __align__(128) float  g_sq[(size_t)2*NN*NN];
__device__ __align__(128) __half g_Wg0h[256*K50], g_Wg0l[256*K50];
__device__ __align__(128) __half g_Wc0h[128*K50], g_Wc0l[128*K50];
__device__ __align__(128) __half g_Wg1h[256*K51], g_Wg1l[256*K51];
__device__ __align__(128) __half g_Wc1h[128*K51], g_Wc1l[128*K51];
__device__ __align__(128) float  g_gate[(size_t)NB*256];
__device__ __align__(128) float  g_s0[(size_t)NB*HH];
__device__ __align__(128) float  g_s1[(size_t)NB*HH];

// ---------------- helpers ----------------
__device__ __forceinline__ uint32_t smem_u32(const void* p){
    uint32_t a; asm("{ .reg .u64 t; cvta.to.shared.u64 t, %1; cvt.u32.u64 %0, t; }":"=r"(a):"l"(p)); return a;
}
__device__ __forceinline__ void cp16(uint32_t d, const void* s){
    asm volatile("cp.async.cg.shared.global [%0], [%1], 16;\n"::"r"(d),"l"(s):"memory");
}
__device__ __forceinline__ void ldmA(uint32_t* a, uint32_t addr){
    asm volatile("ldmatrix.sync.aligned.m8n8.x4.shared.b16 {%0,%1,%2,%3}, [%4];"
        : "=r"(a[0]),"=r"(a[1]),"=r"(a[2]),"=r"(a[3]) : "r"(addr));
}
__device__ __forceinline__ void ldmB(uint32_t* b, uint32_t addr){
    asm volatile("ldmatrix.sync.aligned.m8n8.x2.shared.b16 {%0,%1}, [%2];"
        : "=r"(b[0]),"=r"(b[1]) : "r"(addr));
}
__device__ __forceinline__ void mma16816(float* d, const uint32_t* a, const uint32_t* b){
    asm volatile("mma.sync.aligned.m16n8k16.row.col.f32.f16.f16.f32 "
        "{%0,%1,%2,%3},{%4,%5,%6,%7},{%8,%9},{%0,%1,%2,%3};"
        : "+f"(d[0]),"+f"(d[1]),"+f"(d[2]),"+f"(d[3])
        : "r"(a[0]),"r"(a[1]),"r"(a[2]),"r"(a[3]),"r"(b[0]),"r"(b[1]));
}

// ---------------- fp16-split HGEMM: quad-tile, 2-3 products per K-chunk ----------------
// acc = Ah@Bl^T + Ah@Bh^T [+ Al@Bh^T if nprod==3]; K in chunks of 32; A,B K-major.
// mode 0: split-write Y into g_Ah/g_Al; B rows are (b*fCnt + j), feature f = fLo + j
// mode 1: gate[row*256+c] = sigmoid(v + bias[c])
// mode 2: state[row*128+c] = u*s + (1-u)*tanh(v + bias[c])
struct GArgs {
    const __half *Ah,*Al,*Bh,*Bl;
    int lda, ldb, nch, mode, fp, k5, fLo, fCnt, nprod;
    const float* bias; float* gate; float* state;
};

__global__ __launch_bounds__(256,2) void hgemm(GArgs g)
{
    extern __shared__ __align__(16) __half sm[];
    const int tid = threadIdx.x;
    const int wid = tid >> 5, lane = tid & 31;
    const int m0 = blockIdx.y * 128, n0 = blockIdx.x * 128;
    const int mbase = (wid >> 2) * 64, nbase = (wid & 3) * 32;
    const uint32_t smb = smem_u32(sm);

    float acc[4][4][4];
#pragma unroll
    for (int i = 0; i < 4; i++)
#pragma unroll
        for (int j = 0; j < 4; j++)
#pragma unroll
            for (int k = 0; k < 4; k++) acc[i][j][k] = 0.f;

    const int lr = tid >> 2;
    const int lc = (tid & 3) * 8;

    auto fill = [&](int c, int buf){
        const int k0 = c * 32;
        const __half* srcs[4] = {
            g.Ah + (size_t)m0 * g.lda + k0,
            g.Al + (size_t)m0 * g.lda + k0,
            g.Bh + (size_t)n0 * g.ldb + k0,
            g.Bl + (size_t)n0 * g.ldb + k0 };
        const int lds[4] = { g.lda, g.lda, g.ldb, g.ldb };
        const uint32_t base = smb + buf * 4*TSH*2;
#pragma unroll
        for (int t = 0; t < 4; t++) {
            const uint32_t tb = base + t * TSH*2;
#pragma unroll
            for (int h = 0; h < 2; h++) {
                const int r = lr + h * 64;
                cp16(tb + (r*PITCH + lc)*2, srcs[t] + (size_t)r * lds[t] + lc);
            }
        }
        asm volatile("cp.async.commit_group;\n":::"memory");
    };

    fill(0, 0);
    for (int c = 0; c < g.nch; c++) {
        const int buf = c & 1;
        if (c + 1 < g.nch) {
            fill(c + 1, buf ^ 1);
            asm volatile("cp.async.wait_group 1;\n":::"memory");
        } else {
            asm volatile("cp.async.wait_group 0;\n":::"memory");
        }
        __syncthreads();
        const uint32_t base = smb + buf * 4*TSH*2;
        const uint32_t aH = base, aL = base + TSH*2;
        const uint32_t bH = base + 2*TSH*2, bL = base + 3*TSH*2;
#pragma unroll
        for (int ks = 0; ks < 2; ks++) {
            const int chA = ks*16 + (lane >> 4) * 8;
            const int lB = lane & 15;
            const int chB = ks*16 + (lB >> 3) * 8;
            uint32_t afr[4][4], bfr[4][2];
            // product 1: Ah @ Bl
#pragma unroll
            for (int mi = 0; mi < 4; mi++) {
                const int r = mbase + mi*16 + (lane & 15);
                ldmA(afr[mi], aH + (r*PITCH + chA)*2);
            }
#pragma unroll
            for (int ni = 0; ni < 4; ni++) {
                const int r = nbase + ni*8 + (lB & 7);
                ldmB(bfr[ni], bL + (r*PITCH + chB)*2);
            }
#pragma unroll
            for (int mi = 0; mi < 4; mi++)
#pragma unroll
                for (int ni = 0; ni < 4; ni++)
                    mma16816(acc[mi][ni], afr[mi], bfr[ni]);
            // product 2: Ah @ Bh (reuse afr)
#pragma unroll
            for (int ni = 0; ni < 4; ni++) {
                const int r = nbase + ni*8 + (lB & 7);
                ldmB(bfr[ni], bH + (r*PITCH + chB)*2);
            }
#pragma unroll
            for (int mi = 0; mi < 4; mi++)
#pragma unroll
                for (int ni = 0; ni < 4; ni++)
                    mma16816(acc[mi][ni], afr[mi], bfr[ni]);
            // product 3: Al @ Bh (reuse bfr) — skipped for trimmed gate GEMMs
            if (g.nprod == 3) {
#pragma unroll
                for (int mi = 0; mi < 4; mi++) {
                    const int r = mbase + mi*16 + (lane & 15);
                    ldmA(afr[mi], aL + (r*PITCH + chA)*2);
                }
#pragma unroll
                for (int mi = 0; mi < 4; mi++)
#pragma unroll
                    for (int ni = 0; ni < 4; ni++)
                        mma16816(acc[mi][ni], afr[mi], bfr[ni]);
            }
        }
        __syncthreads();
    }

    // ---------------- epilogue ----------------
#pragma unroll
    for (int mi = 0; mi < 4; mi++) {
#pragma unroll
        for (int h2 = 0; h2 < 2; h2++) {
            const int rg = m0 + mbase + mi*16 + (lane >> 2) + h2*8;
#pragma unroll
            for (int ni = 0; ni < 4; ni++) {
                const int cg = n0 + nbase + ni*8 + (lane & 3)*2;
                const float v0 = acc[mi][ni][h2*2 + 0];
                const float v1 = acc[mi][ni][h2*2 + 1];
                if (g.mode == 0) {
                    const int s = rg >> 10, n = rg & 1023;
                    const int b = cg / g.fCnt;
                    const int f = g.fLo + (cg - b * g.fCnt);
                    const size_t base = (size_t)(n*64 + b) * g.k5 + (size_t)(s+1) * g.fp + f;
                    const __half h0 = __float2half_rn(v0), h1 = __float2half_rn(v1);
                    __half2 hh; hh.x = h0; hh.y = h1;
                    __half2 ll;
                    ll.x = __float2half_rn(v0 - __half2float(h0));
                    ll.y = __float2half_rn(v1 - __half2float(h1));
                    *(__half2*)(g_Ah + base) = hh;
                    *(__half2*)(g_Al + base) = ll;
                } else if (g.mode == 1) {
                    float2 o;
                    o.x = 1.f/(1.f + expf(-(v0 + g.bias[cg+0])));
                    o.y = 1.f/(1.f + expf(-(v1 + g.bias[cg+1])));
                    *(float2*)(g.gate + (size_t)rg*256 + cg) = o;
                } else {
                    const float2 u = *(const float2*)(g.gate + (size_t)rg*256 + 128 + cg);
                    const float2 so = *(const float2*)(g.state + (size_t)rg*128 + cg);
                    float2 o;
                    o.x = u.x*so.x + (1.f-u.x)*tanhf(v0 + g.bias[cg+0]);
                    o.y = u.y*so.y + (1.f-u.y)*tanhf(v1 + g.bias[cg+1]);
                    *(float2*)(g.state + (size_t)rg*128 + cg) = o;
                }
            }
        }
    }
}

// ---------------- fp32 SGEMM for prologue: C = 2 * A @ A (1024^3) ----------------
__global__ __launch_bounds__(256)
void sgemm_sq(const float* __restrict__ A, float* __restrict__ C)
{
    __shared__ float As[2][8][128];
    __shared__ float Bs[2][8][128];
    const int tid = threadIdx.x;
    const int m0 = blockIdx.y * 128, n0 = blockIdx.x * 128;
    const int arow = tid >> 1, acol = (tid & 1) << 2;
    const int brow = tid >> 5, bcol = (tid & 31) << 2;
    const float* Ap = A + (size_t)(m0 + arow) * NN + acol;
    const float* Bp = A + (size_t)brow * NN + n0 + bcol;
    const int tx = tid & 15, ty = tid >> 4;
    float acc[8][8];
#pragma unroll
    for (int i = 0; i < 8; i++)
#pragma unroll
        for (int j = 0; j < 8; j++) acc[i][j] = 0.f;
    float4 a4 = *(const float4*)Ap, b4 = *(const float4*)Bp;
    As[0][acol+0][arow]=a4.x; As[0][acol+1][arow]=a4.y; As[0][acol+2][arow]=a4.z; As[0][acol+3][arow]=a4.w;
    *(float4*)(&Bs[0][brow][bcol]) = b4;
    __syncthreads();
    for (int it = 0; it < 128; ++it) {
        const int buf = it & 1;
        if (it + 1 < 128) {
            const int k0 = (it + 1) << 3;
            a4 = *(const float4*)(Ap + k0);
            b4 = *(const float4*)(Bp + (size_t)k0 * NN);
        }
#pragma unroll
        for (int kk = 0; kk < 8; ++kk) {
            float ar[8], br[8];
            *(float4*)&ar[0] = *(const float4*)&As[buf][kk][ty*8];
            *(float4*)&ar[4] = *(const float4*)&As[buf][kk][ty*8+4];
            *(float4*)&br[0] = *(const float4*)&Bs[buf][kk][tx*8];
            *(float4*)&br[4] = *(const float4*)&Bs[buf][kk][tx*8+4];
#pragma unroll
            for (int i = 0; i < 8; i++)
#pragma unroll
                for (int j = 0; j < 8; j++) acc[i][j] = fmaf(ar[i], br[j], acc[i][j]);
        }
        if (it + 1 < 128) {
            const int nb2 = buf ^ 1;
            As[nb2][acol+0][arow]=a4.x; As[nb2][acol+1][arow]=a4.y; As[nb2][acol+2][arow]=a4.z; As[nb2][acol+3][arow]=a4.w;
            *(float4*)(&Bs[nb2][brow][bcol]) = b4;
            __syncthreads();
        }
    }
#pragma unroll
    for (int i = 0; i < 8; i++) {
        float* Cp = C + (size_t)(m0 + ty*8 + i) * NN + n0 + tx*8;
#pragma unroll
        for (int j = 0; j < 8; j++) Cp[j] = 2.f * acc[i][j];
    }
}

// ---------------- builders ----------------
// layer0 feature order: [s(128), inp(2), pad(30)]
__device__ __forceinline__ float xval0(const float* __restrict__ inp, int n, int b, int f, int reset){
    if (f < 128) {
        float s = g_s0[((size_t)n*64 + b)*HH + f];
        if (reset) s *= g_gate[((size_t)n*64 + b)*256 + f];
        return s;
    }
    if (f < 130) return inp[((size_t)b*NN + n)*2 + (f - 128)];
    return 0.f;
}
// layer1 feature order: [s0(128), s1(128)]
__device__ __forceinline__ float xval1(int n, int b, int f, int reset){
    if (f < HH) return g_s0[((size_t)n*64 + b)*HH + f];
    const int j = f - HH;
    float s = g_s1[((size_t)n*64 + b)*HH + j];
    if (reset) s *= g_gate[((size_t)n*64 + b)*256 + j];
    return s;
}

// Fused: writes A rows (K-major, column f) AND Xt rows (b*fCnt + j)*NN + n, f = fLo + j
__global__ void build_ax(const float* __restrict__ inp, int layer, int reset,
                         int fLo, int fCnt, int k5){
    __shared__ float t[32][33];
    const int b = blockIdx.z, j0 = blockIdx.y*32, nt = blockIdx.x*32;
    const int tx = threadIdx.x, ty = threadIdx.y;
#pragma unroll
    for (int k = 0; k < 4; k++) {
        const int n = nt + ty + 8*k, f = fLo + j0 + tx;
        const float v = layer ? xval1(n, b, f, reset) : xval0(inp, n, b, f, reset);
        t[ty + 8*k][tx] = v;
        __half h = __float2half_rn(v);
        const size_t ao = (size_t)(n*64 + b) * k5 + f;
        g_Ah[ao] = h;
        g_Al[ao] = __float2half_rn(v - __half2float(h));
    }
    __syncthreads();
#pragma unroll
    for (int k = 0; k < 4; k++) {
        const int j = j0 + ty + 8*k, n = nt + tx;
        const float v = t[tx][ty + 8*k];
        __half h = __float2half_rn(v);
        const size_t o = ((size_t)b*fCnt + j)*NN + n;
        g_Xth[o] = h;
        g_Xtl[o] = __float2half_rn(v - __half2float(h));
    }
}

__global__ void split_G(const float* __restrict__ sup){
    size_t i = (size_t)blockIdx.x * blockDim.x + threadIdx.x;
    if (i >= (size_t)4096*NN) return;
    const int row = (int)(i >> 10), col = (int)(i & 1023);
    const int slice = row >> 10, n = row & 1023;
    float v;
    if (slice == 0)      v = sup[(size_t)n*NN + col];
    else if (slice == 1) v = g_sq[(size_t)n*NN + col];
    else if (slice == 2) v = sup[(size_t)NN*NN + (size_t)n*NN + col];
    else                 v = g_sq[(size_t)NN*NN + (size_t)n*NN + col];
    __half h = __float2half_rn(v);
    g_Gh[i] = h;
    g_Gl[i] = __float2half_rn(v - __half2float(h));
}

// swapInp: layer0 reorder — W row for new f: f<128 -> orig 2+f; f in [128,130) -> orig f-128; else 0
__global__ void build_wt(__half* __restrict__ Wh, __half* __restrict__ Wl,
                         const float* __restrict__ src, int O, int F, int fp, int swapInp){
    const int k5 = 5*fp;
    int i = blockIdx.x * blockDim.x + threadIdx.x;
    if (i >= O*k5) return;
    const int o = i / k5, k = i - o*k5;
    const int t = k / fp, f = k - t*fp;
    int fo = f;
    if (swapInp) fo = (f < 128) ? (f + 2) : ((f < 130) ? (f - 128) : F);
    float v = 0.f;
    if (fo < F) {
        #define WSK(s,kx) src[((((size_t)(s))*3 + (kx))*F + fo)*O + o]
        switch (t) {
            case 0: v = WSK(0,0)+WSK(1,0)-WSK(0,2)-WSK(1,2); break;
            case 1: v = WSK(0,1); break;
            case 2: v = WSK(0,2); break;
            case 3: v = WSK(1,1); break;
            case 4: v = WSK(1,2); break;
        }
        #undef WSK
    }
    __half h = __float2half_rn(v);
    Wh[i] = h;
    Wl[i] = __float2half_rn(v - __half2float(h));
}

__global__ void write_out(float* __restrict__ out){
    const int nb = blockIdx.x, h = threadIdx.x;
    const int n = nb >> 6, b = nb & 63;
    out[(((size_t)0*BB + b)*NN + n)*HH + h] = g_s0[(size_t)nb*HH + h];
    out[(((size_t)1*BB + b)*NN + n)*HH + h] = g_s1[(size_t)nb*HH + h];
}

// ---------------- host ----------------
static void run_gemm(dim3 grid, const __half* Ah, const __half* Al,
                     const __half* Bh, const __half* Bl,
                     int lda, int ldb, int nch, int mode, int fp, int k5,
                     int fLo, int fCnt, int nprod,
                     const float* bias, float* gate, float* state)
{
    GArgs g{Ah,Al,Bh,Bl,lda,ldb,nch,mode,fp,k5,fLo,fCnt,nprod,bias,gate,state};
    hgemm<<<grid, 256, SMEM_SZ>>>(g);
}

extern "C" void kernel_launch(void* const* d_in, const int* in_sizes, int n_in,
                              void* d_out, int out_size)
{
    const float* inputs = (const float*)d_in[0];
    const float* sup    = (const float*)d_in[1];
    const float* ruW0 = (const float*)d_in[2];
    const float* rub0 = (const float*)d_in[3];
    const float* hW0  = (const float*)d_in[4];
    const float* hb0  = (const float*)d_in[5];
    const float* ruW1 = (const float*)d_in[6];
    const float* rub1 = (const float*)d_in[7];
    const float* hW1  = (const float*)d_in[8];
    const float* hb1  = (const float*)d_in[9];
    float* out = (float*)d_out;

    cudaFuncSetAttribute(hgemm, cudaFuncAttributeMaxDynamicSharedMemorySize, SMEM_SZ);

    float *SQ, *S0, *S1, *GATE;
    __half *Ah, *Al, *Xth, *Xtl, *Gh, *Gl;
    __half *Wg0h,*Wg0l,*Wc0h,*Wc0l,*Wg1h,*Wg1l,*Wc1h,*Wc1l;
    cudaGetSymbolAddress((void**)&SQ, g_sq);
    cudaGetSymbolAddress((void**)&S0, g_s0);
    cudaGetSymbolAddress((void**)&S1, g_s1);
    cudaGetSymbolAddress((void**)&GATE, g_gate);
    cudaGetSymbolAddress((void**)&Ah, g_Ah);
    cudaGetSymbolAddress((void**)&Al, g_Al);
    cudaGetSymbolAddress((void**)&Xth, g_Xth);
    cudaGetSymbolAddress((void**)&Xtl, g_Xtl);
    cudaGetSymbolAddress((void**)&Gh, g_Gh);
    cudaGetSymbolAddress((void**)&Gl, g_Gl);
    cudaGetSymbolAddress((void**)&Wg0h, g_Wg0h); cudaGetSymbolAddress((void**)&Wg0l, g_Wg0l);
    cudaGetSymbolAddress((void**)&Wc0h, g_Wc0h); cudaGetSymbolAddress((void**)&Wc0l, g_Wc0l);
    cudaGetSymbolAddress((void**)&Wg1h, g_Wg1h); cudaGetSymbolAddress((void**)&Wg1l, g_Wg1l);
    cudaGetSymbolAddress((void**)&Wc1h, g_Wc1h); cudaGetSymbolAddress((void**)&Wc1l, g_Wc1l);

    // prologue
    sgemm_sq<<<dim3(8,8), 256>>>(sup, SQ);
    sgemm_sq<<<dim3(8,8), 256>>>(sup + (size_t)NN*NN, SQ + (size_t)NN*NN);
    split_G<<<(4096*1024)/256, 256>>>(sup);
    build_wt<<<(256*K50+255)/256, 256>>>(Wg0h, Wg0l, ruW0, 256, F0R, FP0, 1);
    build_wt<<<(128*K50+255)/256, 256>>>(Wc0h, Wc0l, hW0, 128, F0R, FP0, 1);
    build_wt<<<(256*K51+255)/256, 256>>>(Wg1h, Wg1l, ruW1, 256, FP1, FP1, 0);
    build_wt<<<(128*K51+255)/256, 256>>>(Wc1h, Wc1l, hW1, 128, FP1, FP1, 0);
    cudaMemsetAsync(S0, 0, (size_t)NB*HH*4);
    cudaMemsetAsync(S1, 0, (size_t)NB*HH*4);

    const dim3 gg0(BF0/128, 32);        // (80, 32)  layer0 gate graph
    const dim3 gg1(BF1/128, 32);        // (128, 32) layer1 gate graph
    const dim3 gcand(64, 32);           // candidate graph (128 feats x 64 batch)
    const dim3 wgate(2, 512), wcand(1, 512);
    const dim3 bxt(32, 8);

    for (int t = 0; t < 12; ++t) {
        const float* inp = inputs + (size_t)t * BB * NN * 2;
        // ---- layer 0 gate: full X (trimmed graph: Y reuse cols are only inp/pads) ----
        build_ax<<<dim3(32, FP0/32, BB), bxt>>>(inp, 0, 0, 0, FP0, K50);
        run_gemm(gg0, Gh, Gl, Xth, Xtl, NN, NN, 32, 0, FP0, K50, 0, FP0, 2, 0, 0, 0);
        run_gemm(wgate, Ah, Al, Wg0h, Wg0l, K50, K50, 25, 1, FP0, K50, 0, 0, 2, rub0, GATE, 0);
        // ---- layer 0 candidate: only s-features (f 0..127) change; exact ----
        build_ax<<<dim3(32, 4, BB), bxt>>>(inp, 0, 1, 0, 128, K50);
        run_gemm(gcand, Gh, Gl, Xth, Xtl, NN, NN, 32, 0, FP0, K50, 0, 128, 3, 0, 0, 0);
        run_gemm(wcand, Ah, Al, Wc0h, Wc0l, K50, K50, 25, 2, FP0, K50, 0, 0, 3, hb0, GATE, S0);
        // ---- layer 1 gate: full X (graph EXACT: s0-cols of Y reused by cand weight GEMM) ----
        build_ax<<<dim3(32, FP1/32, BB), bxt>>>(inp, 1, 0, 0, FP1, K51);
        run_gemm(gg1, Gh, Gl, Xth, Xtl, NN, NN, 32, 0, FP1, K51, 0, FP1, 3, 0, 0, 0);
        run_gemm(wgate, Ah, Al, Wg1h, Wg1l, K51, K51, 40, 1, FP1, K51, 0, 0, 2, rub1, GATE, 0);
        // ---- layer 1 candidate: only s1-features (f 128..255) change; exact ----
        build_ax<<<dim3(32, 4, BB), bxt>>>(inp, 1, 1, 128, 128, K51);
        run_gemm(gcand, Gh, Gl, Xth, Xtl, NN, NN, 32, 0, FP1, K51, 128, 128, 3, 0, 0, 0);
        run_gemm(wcand, Ah, Al, Wc1h, Wc1l, K51, K51, 40, 2, FP1, K51, 0, 0, 3, hb1, GATE, S1);
    }
    write_out<<<NB, 128>>>(out);
}

// round 15
// speedup vs baseline: 1.2663x; 1.0529x over previous
#include <cuda_runtime.h>
#include <cuda_fp16.h>
#include <math.h>
#include <stdint.h>

#define NN 1024
#define BB 64
#define NB 65536
#define HH 128
#define F0R 130
#define FP0 160                  // layer0 padded features, [s(128), inp(2), 0...]
#define FP1 256
#define BF1 (BB*FP1)             // 16384
#define K50 (5*FP0)              // 800
#define K51 (5*FP1)              // 1280
#define PITCH 40                 // halves per smem row (80B, 16B-aligned, conflict-free)
#define TSH (128*PITCH)
#define SMEM_SZ (2*4*TSH*2)      // 81920

// ---------------- static device scratch ----------------
__device__ __align__(128) __half g_Ah[(size_t)NB*K51];
__device__ __align__(128) __half g_Al[(size_t)NB*K51];
__device__ __align__(128) __half g_Xth[(size_t)BF1*NN];
__device__ __align__(128) __half g_Xtl[(size_t)BF1*NN];
__device__ __align__(128) __half g_Gh[(size_t)4096*NN];
__device__ __align__(128) __half g_Gl[(size_t)4096*NN];
__device__ __align__(128) float  g_sq[(size_t)2*NN*NN];
__device__ __align__(128) __half g_Wg0h[256*K50], g_Wg0l[256*K50];
__device__ __align__(128) __half g_Wc0h[128*K50], g_Wc0l[128*K50];
__device__ __align__(128) __half g_Wg1h[256*K51], g_Wg1l[256*K51];
__device__ __align__(128) __half g_Wc1h[128*K51], g_Wc1l[128*K51];
__device__ __align__(128) float  g_gate[(size_t)NB*256];
__device__ __align__(128) float  g_s0[(size_t)NB*HH];
__device__ __align__(128) float  g_s1[(size_t)NB*HH];

// ---------------- helpers ----------------
__device__ __forceinline__ uint32_t smem_u32(const void* p){
    uint32_t a; asm("{ .reg .u64 t; cvta.to.shared.u64 t, %1; cvt.u32.u64 %0, t; }":"=r"(a):"l"(p)); return a;
}
__device__ __forceinline__ void cp16(uint32_t d, const void* s){
    asm volatile("cp.async.cg.shared.global [%0], [%1], 16;\n"::"r"(d),"l"(s):"memory");
}
__device__ __forceinline__ void ldmA(uint32_t* a, uint32_t addr){
    asm volatile("ldmatrix.sync.aligned.m8n8.x4.shared.b16 {%0,%1,%2,%3}, [%4];"
        : "=r"(a[0]),"=r"(a[1]),"=r"(a[2]),"=r"(a[3]) : "r"(addr));
}
__device__ __forceinline__ void ldmB(uint32_t* b, uint32_t addr){
    asm volatile("ldmatrix.sync.aligned.m8n8.x2.shared.b16 {%0,%1}, [%2];"
        : "=r"(b[0]),"=r"(b[1]) : "r"(addr));
}
__device__ __forceinline__ void mma16816(float* d, const uint32_t* a, const uint32_t* b){
    asm volatile("mma.sync.aligned.m16n8k16.row.col.f32.f16.f16.f32 "
        "{%0,%1,%2,%3},{%4,%5,%6,%7},{%8,%9},{%0,%1,%2,%3};"
        : "+f"(d[0]),"+f"(d[1]),"+f"(d[2]),"+f"(d[3])
        : "r"(a[0]),"r"(a[1]),"r"(a[2]),"r"(a[3]),"r"(b[0]),"r"(b[1]));
}

// ---------------- fp16-split HGEMM: quad-tile, 2-3 products per K-chunk ----------------
// acc = Ah@Bl^T + Ah@Bh^T [+ Al@Bh^T if effective nprod==3]
// trimOdd: blocks with odd blockIdx.x use nprod=2 (their output columns feed only sigmoid gates)
// mode 0: split-write Y into g_Ah/g_Al; B rows are (b*fCnt + j), feature f = fLo + j
// mode 1: gate[row*256+c] = sigmoid(v + bias[c])
// mode 2: state[row*128+c] = u*s + (1-u)*tanh(v + bias[c])
struct GArgs {
    const __half *Ah,*Al,*Bh,*Bl;
    int lda, ldb, nch, mode, fp, k5, fLo, fCnt, nprod, trimOdd;
    const float* bias; float* gate; float* state;
};

__global__ __launch_bounds__(256,2) void hgemm(GArgs g)
{
    extern __shared__ __align__(16) __half sm[];
    const int tid = threadIdx.x;
    const int wid = tid >> 5, lane = tid & 31;
    const int m0 = blockIdx.y * 128, n0 = blockIdx.x * 128;
    const int mbase = (wid >> 2) * 64, nbase = (wid & 3) * 32;
    const uint32_t smb = smem_u32(sm);
    const int np = (g.trimOdd && (blockIdx.x & 1)) ? 2 : g.nprod;

    float acc[4][4][4];
#pragma unroll
    for (int i = 0; i < 4; i++)
#pragma unroll
        for (int j = 0; j < 4; j++)
#pragma unroll
            for (int k = 0; k < 4; k++) acc[i][j][k] = 0.f;

    const int lr = tid >> 2;
    const int lc = (tid & 3) * 8;

    auto fill = [&](int c, int buf){
        const int k0 = c * 32;
        const __half* srcs[4] = {
            g.Ah + (size_t)m0 * g.lda + k0,
            g.Al + (size_t)m0 * g.lda + k0,
            g.Bh + (size_t)n0 * g.ldb + k0,
            g.Bl + (size_t)n0 * g.ldb + k0 };
        const int lds[4] = { g.lda, g.lda, g.ldb, g.ldb };
        const uint32_t base = smb + buf * 4*TSH*2;
#pragma unroll
        for (int t = 0; t < 4; t++) {
            const uint32_t tb = base + t * TSH*2;
#pragma unroll
            for (int h = 0; h < 2; h++) {
                const int r = lr + h * 64;
                cp16(tb + (r*PITCH + lc)*2, srcs[t] + (size_t)r * lds[t] + lc);
            }
        }
        asm volatile("cp.async.commit_group;\n":::"memory");
    };

    fill(0, 0);
    for (int c = 0; c < g.nch; c++) {
        const int buf = c & 1;
        if (c + 1 < g.nch) {
            fill(c + 1, buf ^ 1);
            asm volatile("cp.async.wait_group 1;\n":::"memory");
        } else {
            asm volatile("cp.async.wait_group 0;\n":::"memory");
        }
        __syncthreads();
        const uint32_t base = smb + buf * 4*TSH*2;
        const uint32_t aH = base, aL = base + TSH*2;
        const uint32_t bH = base + 2*TSH*2, bL = base + 3*TSH*2;
#pragma unroll
        for (int ks = 0; ks < 2; ks++) {
            const int chA = ks*16 + (lane >> 4) * 8;
            const int lB = lane & 15;
            const int chB = ks*16 + (lB >> 3) * 8;
            uint32_t afr[4][4], bfr[4][2];
            // product 1: Ah @ Bl
#pragma unroll
            for (int mi = 0; mi < 4; mi++) {
                const int r = mbase + mi*16 + (lane & 15);
                ldmA(afr[mi], aH + (r*PITCH + chA)*2);
            }
#pragma unroll
            for (int ni = 0; ni < 4; ni++) {
                const int r = nbase + ni*8 + (lB & 7);
                ldmB(bfr[ni], bL + (r*PITCH + chB)*2);
            }
#pragma unroll
            for (int mi = 0; mi < 4; mi++)
#pragma unroll
                for (int ni = 0; ni < 4; ni++)
                    mma16816(acc[mi][ni], afr[mi], bfr[ni]);
            // product 2: Ah @ Bh (reuse afr)
#pragma unroll
            for (int ni = 0; ni < 4; ni++) {
                const int r = nbase + ni*8 + (lB & 7);
                ldmB(bfr[ni], bH + (r*PITCH + chB)*2);
            }
#pragma unroll
            for (int mi = 0; mi < 4; mi++)
#pragma unroll
                for (int ni = 0; ni < 4; ni++)
                    mma16816(acc[mi][ni], afr[mi], bfr[ni]);
            // product 3: Al @ Bh (reuse bfr) — skipped where output feeds only sigmoids
            if (np == 3) {
#pragma unroll
                for (int mi = 0; mi < 4; mi++) {
                    const int r = mbase + mi*16 + (lane & 15);
                    ldmA(afr[mi], aL + (r*PITCH + chA)*2);
                }
#pragma unroll
                for (int mi = 0; mi < 4; mi++)
#pragma unroll
                    for (int ni = 0; ni < 4; ni++)
                        mma16816(acc[mi][ni], afr[mi], bfr[ni]);
            }
        }
        __syncthreads();
    }

    // ---------------- epilogue ----------------
#pragma unroll
    for (int mi = 0; mi < 4; mi++) {
#pragma unroll
        for (int h2 = 0; h2 < 2; h2++) {
            const int rg = m0 + mbase + mi*16 + (lane >> 2) + h2*8;
#pragma unroll
            for (int ni = 0; ni < 4; ni++) {
                const int cg = n0 + nbase + ni*8 + (lane & 3)*2;
                const float v0 = acc[mi][ni][h2*2 + 0];
                const float v1 = acc[mi][ni][h2*2 + 1];
                if (g.mode == 0) {
                    const int s = rg >> 10, n = rg & 1023;
                    const int b = cg / g.fCnt;
                    const int f = g.fLo + (cg - b * g.fCnt);
                    const size_t base = (size_t)(n*64 + b) * g.k5 + (size_t)(s+1) * g.fp + f;
                    const __half h0 = __float2half_rn(v0), h1 = __float2half_rn(v1);
                    __half2 hh; hh.x = h0; hh.y = h1;
                    __half2 ll;
                    ll.x = __float2half_rn(v0 - __half2float(h0));
                    ll.y = __float2half_rn(v1 - __half2float(h1));
                    *(__half2*)(g_Ah + base) = hh;
                    *(__half2*)(g_Al + base) = ll;
                } else if (g.mode == 1) {
                    float2 o;
                    o.x = 1.f/(1.f + expf(-(v0 + g.bias[cg+0])));
                    o.y = 1.f/(1.f + expf(-(v1 + g.bias[cg+1])));
                    *(float2*)(g.gate + (size_t)rg*256 + cg) = o;
                } else {
                    const float2 u = *(const float2*)(g.gate + (size_t)rg*256 + 128 + cg);
                    const float2 so = *(const float2*)(g.state + (size_t)rg*128 + cg);
                    float2 o;
                    o.x = u.x*so.x + (1.f-u.x)*tanhf(v0 + g.bias[cg+0]);
                    o.y = u.y*so.y + (1.f-u.y)*tanhf(v1 + g.bias[cg+1]);
                    *(float2*)(g.state + (size_t)rg*128 + cg) = o;
                }
            }
        }
    }
}

// ---------------- fp32 SGEMM for prologue: C = 2 * A @ A (1024^3) ----------------
__global__ __launch_bounds__(256)
void sgemm_sq(const float* __restrict__ A, float* __restrict__ C)
{
    __shared__ float As[2][8][128];
    __shared__ float Bs[2][8][128];
    const int tid = threadIdx.x;
    const int m0 = blockIdx.y * 128, n0 = blockIdx.x * 128;
    const int arow = tid >> 1, acol = (tid & 1) << 2;
    const int brow = tid >> 5, bcol = (tid & 31) << 2;
    const float* Ap = A + (size_t)(m0 + arow) * NN + acol;
    const float* Bp = A + (size_t)brow * NN + n0 + bcol;
    const int tx = tid & 15, ty = tid >> 4;
    float acc[8][8];
#pragma unroll
    for (int i = 0; i < 8; i++)
#pragma unroll
        for (int j = 0; j < 8; j++) acc[i][j] = 0.f;
    float4 a4 = *(const float4*)Ap, b4 = *(const float4*)Bp;
    As[0][acol+0][arow]=a4.x; As[0][acol+1][arow]=a4.y; As[0][acol+2][arow]=a4.z; As[0][acol+3][arow]=a4.w;
    *(float4*)(&Bs[0][brow][bcol]) = b4;
    __syncthreads();
    for (int it = 0; it < 128; ++it) {
        const int buf = it & 1;
        if (it + 1 < 128) {
            const int k0 = (it + 1) << 3;
            a4 = *(const float4*)(Ap + k0);
            b4 = *(const float4*)(Bp + (size_t)k0 * NN);
        }
#pragma unroll
        for (int kk = 0; kk < 8; ++kk) {
            float ar[8], br[8];
            *(float4*)&ar[0] = *(const float4*)&As[buf][kk][ty*8];
            *(float4*)&ar[4] = *(const float4*)&As[buf][kk][ty*8+4];
            *(float4*)&br[0] = *(const float4*)&Bs[buf][kk][tx*8];
            *(float4*)&br[4] = *(const float4*)&Bs[buf][kk][tx*8+4];
#pragma unroll
            for (int i = 0; i < 8; i++)
#pragma unroll
                for (int j = 0; j < 8; j++) acc[i][j] = fmaf(ar[i], br[j], acc[i][j]);
        }
        if (it + 1 < 128) {
            const int nb2 = buf ^ 1;
            As[nb2][acol+0][arow]=a4.x; As[nb2][acol+1][arow]=a4.y; As[nb2][acol+2][arow]=a4.z; As[nb2][acol+3][arow]=a4.w;
            *(float4*)(&Bs[nb2][brow][bcol]) = b4;
            __syncthreads();
        }
    }
#pragma unroll
    for (int i = 0; i < 8; i++) {
        float* Cp = C + (size_t)(m0 + ty*8 + i) * NN + n0 + tx*8;
#pragma unroll
        for (int j = 0; j < 8; j++) Cp[j] = 2.f * acc[i][j];
    }
}

// ---------------- builders ----------------
// layer0 feature order: [s(128), inp(2), pad(30)]
__device__ __forceinline__ float xval0(const float* __restrict__ inp, int n, int b, int f, int reset){
    if (f < 128) {
        float s = g_s0[((size_t)n*64 + b)*HH + f];
        if (reset) s *= g_gate[((size_t)n*64 + b)*256 + f];
        return s;
    }
    if (f < 130) return inp[((size_t)b*NN + n)*2 + (f - 128)];
    return 0.f;
}
// layer1 feature order: [s0(128), s1(128)]
__device__ __forceinline__ float xval1(int n, int b, int f, int reset){
    if (f < HH) return g_s0[((size_t)n*64 + b)*HH + f];
    const int j = f - HH;
    float s = g_s1[((size_t)n*64 + b)*HH + j];
    if (reset) s *= g_gate[((size_t)n*64 + b)*256 + j];
    return s;
}

// Fused: writes A cols [fLo, fLo+fA) AND Xt rows (b*fCnt + j)*NN + n for j < fCnt
__global__ void build_ax(const float* __restrict__ inp, int layer, int reset,
                         int fLo, int fCnt, int fA, int k5){
    __shared__ float t[32][33];
    const int b = blockIdx.z, j0 = blockIdx.y*32, nt = blockIdx.x*32;
    const int tx = threadIdx.x, ty = threadIdx.y;
#pragma unroll
    for (int k = 0; k < 4; k++) {
        const int n = nt + ty + 8*k, f = fLo + j0 + tx;
        const float v = layer ? xval1(n, b, f, reset) : xval0(inp, n, b, f, reset);
        t[ty + 8*k][tx] = v;
        if (j0 + tx < fA) {
            __half h = __float2half_rn(v);
            const size_t ao = (size_t)(n*64 + b) * k5 + f;
            g_Ah[ao] = h;
            g_Al[ao] = __float2half_rn(v - __half2float(h));
        }
    }
    __syncthreads();
#pragma unroll
    for (int k = 0; k < 4; k++) {
        const int j = j0 + ty + 8*k, n = nt + tx;
        if (j < fCnt) {
            const float v = t[tx][ty + 8*k];
            __half h = __float2half_rn(v);
            const size_t o = ((size_t)b*fCnt + j)*NN + n;
            g_Xth[o] = h;
            g_Xtl[o] = __float2half_rn(v - __half2float(h));
        }
    }
}

__global__ void split_G(const float* __restrict__ sup){
    size_t i = (size_t)blockIdx.x * blockDim.x + threadIdx.x;
    if (i >= (size_t)4096*NN) return;
    const int row = (int)(i >> 10), col = (int)(i & 1023);
    const int slice = row >> 10, n = row & 1023;
    float v;
    if (slice == 0)      v = sup[(size_t)n*NN + col];
    else if (slice == 1) v = g_sq[(size_t)n*NN + col];
    else if (slice == 2) v = sup[(size_t)NN*NN + (size_t)n*NN + col];
    else                 v = g_sq[(size_t)NN*NN + (size_t)n*NN + col];
    __half h = __float2half_rn(v);
    g_Gh[i] = h;
    g_Gl[i] = __float2half_rn(v - __half2float(h));
}

// swapInp: layer0 reorder — W row for new f: f<128 -> orig 2+f; f in [128,130) -> orig f-128; else 0
__global__ void build_wt(__half* __restrict__ Wh, __half* __restrict__ Wl,
                         const float* __restrict__ src, int O, int F, int fp, int swapInp){
    const int k5 = 5*fp;
    int i = blockIdx.x * blockDim.x + threadIdx.x;
    if (i >= O*k5) return;
    const int o = i / k5, k = i - o*k5;
    const int t = k / fp, f = k - t*fp;
    int fo = f;
    if (swapInp) fo = (f < 128) ? (f + 2) : ((f < 130) ? (f - 128) : F);
    float v = 0.f;
    if (fo < F) {
        #define WSK(s,kx) src[((((size_t)(s))*3 + (kx))*F + fo)*O + o]
        switch (t) {
            case 0: v = WSK(0,0)+WSK(1,0)-WSK(0,2)-WSK(1,2); break;
            case 1: v = WSK(0,1); break;
            case 2: v = WSK(0,2); break;
            case 3: v = WSK(1,1); break;
            case 4: v = WSK(1,2); break;
        }
        #undef WSK
    }
    __half h = __float2half_rn(v);
    Wh[i] = h;
    Wl[i] = __float2half_rn(v - __half2float(h));
}

__global__ void write_out(float* __restrict__ out){
    const int nb = blockIdx.x, h = threadIdx.x;
    const int n = nb >> 6, b = nb & 63;
    out[(((size_t)0*BB + b)*NN + n)*HH + h] = g_s0[(size_t)nb*HH + h];
    out[(((size_t)1*BB + b)*NN + n)*HH + h] = g_s1[(size_t)nb*HH + h];
}

// ---------------- host ----------------
static void run_gemm(dim3 grid, const __half* Ah, const __half* Al,
                     const __half* Bh, const __half* Bl,
                     int lda, int ldb, int nch, int mode, int fp, int k5,
                     int fLo, int fCnt, int nprod, int trimOdd,
                     const float* bias, float* gate, float* state)
{
    GArgs g{Ah,Al,Bh,Bl,lda,ldb,nch,mode,fp,k5,fLo,fCnt,nprod,trimOdd,bias,gate,state};
    hgemm<<<grid, 256, SMEM_SZ>>>(g);
}

extern "C" void kernel_launch(void* const* d_in, const int* in_sizes, int n_in,
                              void* d_out, int out_size)
{
    const float* inputs = (const float*)d_in[0];
    const float* sup    = (const float*)d_in[1];
    const float* ruW0 = (const float*)d_in[2];
    const float* rub0 = (const float*)d_in[3];
    const float* hW0  = (const float*)d_in[4];
    const float* hb0  = (const float*)d_in[5];
    const float* ruW1 = (const float*)d_in[6];
    const float* rub1 = (const float*)d_in[7];
    const float* hW1  = (const float*)d_in[8];
    const float* hb1  = (const float*)d_in[9];
    float* out = (float*)d_out;

    cudaFuncSetAttribute(hgemm, cudaFuncAttributeMaxDynamicSharedMemorySize, SMEM_SZ);

    float *SQ, *S0, *S1, *GATE;
    __half *Ah, *Al, *Xth, *Xtl, *Gh, *Gl;
    __half *Wg0h,*Wg0l,*Wc0h,*Wc0l,*Wg1h,*Wg1l,*Wc1h,*Wc1l;
    cudaGetSymbolAddress((void**)&SQ, g_sq);
    cudaGetSymbolAddress((void**)&S0, g_s0);
    cudaGetSymbolAddress((void**)&S1, g_s1);
    cudaGetSymbolAddress((void**)&GATE, g_gate);
    cudaGetSymbolAddress((void**)&Ah, g_Ah);
    cudaGetSymbolAddress((void**)&Al, g_Al);
    cudaGetSymbolAddress((void**)&Xth, g_Xth);
    cudaGetSymbolAddress((void**)&Xtl, g_Xtl);
    cudaGetSymbolAddress((void**)&Gh, g_Gh);
    cudaGetSymbolAddress((void**)&Gl, g_Gl);
    cudaGetSymbolAddress((void**)&Wg0h, g_Wg0h); cudaGetSymbolAddress((void**)&Wg0l, g_Wg0l);
    cudaGetSymbolAddress((void**)&Wc0h, g_Wc0h); cudaGetSymbolAddress((void**)&Wc0l, g_Wc0l);
    cudaGetSymbolAddress((void**)&Wg1h, g_Wg1h); cudaGetSymbolAddress((void**)&Wg1l, g_Wg1l);
    cudaGetSymbolAddress((void**)&Wc1h, g_Wc1h); cudaGetSymbolAddress((void**)&Wc1l, g_Wc1l);

    // prologue
    sgemm_sq<<<dim3(8,8), 256>>>(sup, SQ);
    sgemm_sq<<<dim3(8,8), 256>>>(sup + (size_t)NN*NN, SQ + (size_t)NN*NN);
    split_G<<<(4096*1024)/256, 256>>>(sup);
    build_wt<<<(256*K50+255)/256, 256>>>(Wg0h, Wg0l, ruW0, 256, F0R, FP0, 1);
    build_wt<<<(128*K50+255)/256, 256>>>(Wc0h, Wc0l, hW0, 128, F0R, FP0, 1);
    build_wt<<<(256*K51+255)/256, 256>>>(Wg1h, Wg1l, ruW1, 256, FP1, FP1, 0);
    build_wt<<<(128*K51+255)/256, 256>>>(Wc1h, Wc1l, hW1, 128, FP1, FP1, 0);
    cudaMemsetAsync(S0, 0, (size_t)NB*HH*4);
    cudaMemsetAsync(S1, 0, (size_t)NB*HH*4);

    const dim3 gg0(65, 32);             // layer0 gate graph: 64*130/128 = 65 cols blocks
    const dim3 gg1(BF1/128, 32);        // (128, 32) layer1 gate graph
    const dim3 gcand(64, 32);           // candidate graph (128 feats x 64 batch)
    const dim3 wgate(2, 512), wcand(1, 512);
    const dim3 bxt(32, 8);

    for (int t = 0; t < 12; ++t) {
        const float* inp = inputs + (size_t)t * BB * NN * 2;
        // ---- layer 0 gate: Xt over 130 real features (pads dropped); trimmed graph ----
        build_ax<<<dim3(32, 5, BB), bxt>>>(inp, 0, 0, 0, 130, FP0, K50);
        run_gemm(gg0, Gh, Gl, Xth, Xtl, NN, NN, 32, 0, FP0, K50, 0, 130, 2, 0, 0, 0, 0);
        run_gemm(wgate, Ah, Al, Wg0h, Wg0l, K50, K50, 25, 1, FP0, K50, 0, 0, 2, 0, rub0, GATE, 0);
        // ---- layer 0 candidate: only s-features (f 0..127) change; exact ----
        build_ax<<<dim3(32, 4, BB), bxt>>>(inp, 0, 1, 0, 128, 128, K50);
        run_gemm(gcand, Gh, Gl, Xth, Xtl, NN, NN, 32, 0, FP0, K50, 0, 128, 3, 0, 0, 0, 0);
        run_gemm(wcand, Ah, Al, Wc0h, Wc0l, K50, K50, 25, 2, FP0, K50, 0, 0, 3, 0, hb0, GATE, S0);
        // ---- layer 1 gate: even blocks (s0 Y cols, reused by cand weight) exact;
        //      odd blocks (s1 Y cols, gates only) trimmed ----
        build_ax<<<dim3(32, FP1/32, BB), bxt>>>(inp, 1, 0, 0, FP1, FP1, K51);
        run_gemm(gg1, Gh, Gl, Xth, Xtl, NN, NN, 32, 0, FP1, K51, 0, FP1, 3, 1, 0, 0, 0);
        run_gemm(wgate, Ah, Al, Wg1h, Wg1l, K51, K51, 40, 1, FP1, K51, 0, 0, 2, 0, rub1, GATE, 0);
        // ---- layer 1 candidate: only s1-features (f 128..255) change; exact ----
        build_ax<<<dim3(32, 4, BB), bxt>>>(inp, 1, 1, 128, 128, 128, K51);
        run_gemm(gcand, Gh, Gl, Xth, Xtl, NN, NN, 32, 0, FP1, K51, 128, 128, 3, 0, 0, 0, 0);
        run_gemm(wcand, Ah, Al, Wc1h, Wc1l, K51, K51, 40, 2, FP1, K51, 0, 0, 3, 0, hb1, GATE, S1);
    }
    write_out<<<NB, 128>>>(out);
}

// round 16
// speedup vs baseline: 1.4165x; 1.1186x over previous
#include <cuda_runtime.h>
#include <cuda_fp16.h>
#include <math.h>
#include <stdint.h>

#define NN 1024
#define BB 64
#define NB 65536
#define HH 128
#define F0R 130
#define FP0 160                  // layer0 padded features, [s(128), inp(2), 0...]
#define FP1 256
#define BF1 (BB*FP1)             // 16384
#define K50 (5*FP0)              // 800
#define K51 (5*FP1)              // 1280
#define PITCH 40                 // halves per smem row (80B, 16B-aligned, conflict-free)
#define TSH (128*PITCH)
#define SMEM_SZ (2*4*TSH*2)      // 81920

// ---------------- static device scratch ----------------
__device__ __align__(128) __half g_Ah[(size_t)NB*K51];
__device__ __align__(128) __half g_Al[(size_t)NB*K51];
__device__ __align__(128) __half g_Xth[(size_t)BF1*NN];
__device__ __align__(128) __half g_Xtl[(size_t)BF1*NN];
__device__ __align__(128) __half g_Gh[(size_t)4096*NN];
__device__ __align__(128) __half g_Gl[(size_t)4096*NN];
__device__ __align__(128) float  g_sq[(size_t)2*NN*NN];
__device__ __align__(128) __half g_Wg0h[256*K50], g_Wg0l[256*K50];
__device__ __align__(128) __half g_Wc0h[128*K50], g_Wc0l[128*K50];
__device__ __align__(128) __half g_Wg1h[256*K51], g_Wg1l[256*K51];
__device__ __align__(128) __half g_Wc1h[128*K51], g_Wc1l[128*K51];
__device__ __align__(128) float  g_gate[(size_t)NB*256];
__device__ __align__(128) float  g_s0[(size_t)NB*HH];
__device__ __align__(128) float  g_s1[(size_t)NB*HH];

// ---------------- helpers ----------------
__device__ __forceinline__ uint32_t smem_u32(const void* p){
    uint32_t a; asm("{ .reg .u64 t; cvta.to.shared.u64 t, %1; cvt.u32.u64 %0, t; }":"=r"(a):"l"(p)); return a;
}
__device__ __forceinline__ void cp16(uint32_t d, const void* s){
    asm volatile("cp.async.cg.shared.global [%0], [%1], 16;\n"::"r"(d),"l"(s):"memory");
}
__device__ __forceinline__ void ldmA(uint32_t* a, uint32_t addr){
    asm volatile("ldmatrix.sync.aligned.m8n8.x4.shared.b16 {%0,%1,%2,%3}, [%4];"
        : "=r"(a[0]),"=r"(a[1]),"=r"(a[2]),"=r"(a[3]) : "r"(addr));
}
__device__ __forceinline__ void ldmB(uint32_t* b, uint32_t addr){
    asm volatile("ldmatrix.sync.aligned.m8n8.x2.shared.b16 {%0,%1}, [%2];"
        : "=r"(b[0]),"=r"(b[1]) : "r"(addr));
}
__device__ __forceinline__ void mma16816(float* d, const uint32_t* a, const uint32_t* b){
    asm volatile("mma.sync.aligned.m16n8k16.row.col.f32.f16.f16.f32 "
        "{%0,%1,%2,%3},{%4,%5,%6,%7},{%8,%9},{%0,%1,%2,%3};"
        : "+f"(d[0]),"+f"(d[1]),"+f"(d[2]),"+f"(d[3])
        : "r"(a[0]),"r"(a[1]),"r"(a[2]),"r"(a[3]),"r"(b[0]),"r"(b[1]));
}

// ---------------- fp16-split HGEMM: quad-tile, 2-3 products per K-chunk ----------------
// acc = Ah@Bl^T + Ah@Bh^T [+ Al@Bh^T if effective nprod==3]
// trimOdd: blocks with odd blockIdx.x use nprod=2 (their output columns feed only sigmoid gates)
// np==2 blocks skip loading the Al tile entirely (no product reads it).
// mode 0: split-write Y into g_Ah/g_Al; B rows are (b*fCnt + j), feature f = fLo + j
// mode 1: gate[row*256+c] = sigmoid(v + bias[c])
// mode 2: state[row*128+c] = u*s + (1-u)*tanh(v + bias[c])
struct GArgs {
    const __half *Ah,*Al,*Bh,*Bl;
    int lda, ldb, nch, mode, fp, k5, fLo, fCnt, nprod, trimOdd;
    const float* bias; float* gate; float* state;
};

__global__ __launch_bounds__(256,2) void hgemm(GArgs g)
{
    extern __shared__ __align__(16) __half sm[];
    const int tid = threadIdx.x;
    const int wid = tid >> 5, lane = tid & 31;
    const int m0 = blockIdx.y * 128, n0 = blockIdx.x * 128;
    const int mbase = (wid >> 2) * 64, nbase = (wid & 3) * 32;
    const uint32_t smb = smem_u32(sm);
    const int np = (g.trimOdd && (blockIdx.x & 1)) ? 2 : g.nprod;

    float acc[4][4][4];
#pragma unroll
    for (int i = 0; i < 4; i++)
#pragma unroll
        for (int j = 0; j < 4; j++)
#pragma unroll
            for (int k = 0; k < 4; k++) acc[i][j][k] = 0.f;

    const int lr = tid >> 2;
    const int lc = (tid & 3) * 8;

    auto fill = [&](int c, int buf){
        const int k0 = c * 32;
        const __half* srcs[4] = {
            g.Ah + (size_t)m0 * g.lda + k0,
            g.Al + (size_t)m0 * g.lda + k0,
            g.Bh + (size_t)n0 * g.ldb + k0,
            g.Bl + (size_t)n0 * g.ldb + k0 };
        const int lds[4] = { g.lda, g.lda, g.ldb, g.ldb };
        const uint32_t base = smb + buf * 4*TSH*2;
#pragma unroll
        for (int t = 0; t < 4; t++) {
            if (t == 1 && np == 2) continue;   // Al tile unused when trimmed
            const uint32_t tb = base + t * TSH*2;
#pragma unroll
            for (int h = 0; h < 2; h++) {
                const int r = lr + h * 64;
                cp16(tb + (r*PITCH + lc)*2, srcs[t] + (size_t)r * lds[t] + lc);
            }
        }
        asm volatile("cp.async.commit_group;\n":::"memory");
    };

    fill(0, 0);
    for (int c = 0; c < g.nch; c++) {
        const int buf = c & 1;
        if (c + 1 < g.nch) {
            fill(c + 1, buf ^ 1);
            asm volatile("cp.async.wait_group 1;\n":::"memory");
        } else {
            asm volatile("cp.async.wait_group 0;\n":::"memory");
        }
        __syncthreads();
        const uint32_t base = smb + buf * 4*TSH*2;
        const uint32_t aH = base, aL = base + TSH*2;
        const uint32_t bH = base + 2*TSH*2, bL = base + 3*TSH*2;
#pragma unroll
        for (int ks = 0; ks < 2; ks++) {
            const int chA = ks*16 + (lane >> 4) * 8;
            const int lB = lane & 15;
            const int chB = ks*16 + (lB >> 3) * 8;
            uint32_t afr[4][4], bfr[4][2];
            // product 1: Ah @ Bl
#pragma unroll
            for (int mi = 0; mi < 4; mi++) {
                const int r = mbase + mi*16 + (lane & 15);
                ldmA(afr[mi], aH + (r*PITCH + chA)*2);
            }
#pragma unroll
            for (int ni = 0; ni < 4; ni++) {
                const int r = nbase + ni*8 + (lB & 7);
                ldmB(bfr[ni], bL + (r*PITCH + chB)*2);
            }
#pragma unroll
            for (int mi = 0; mi < 4; mi++)
#pragma unroll
                for (int ni = 0; ni < 4; ni++)
                    mma16816(acc[mi][ni], afr[mi], bfr[ni]);
            // product 2: Ah @ Bh (reuse afr)
#pragma unroll
            for (int ni = 0; ni < 4; ni++) {
                const int r = nbase + ni*8 + (lB & 7);
                ldmB(bfr[ni], bH + (r*PITCH + chB)*2);
            }
#pragma unroll
            for (int mi = 0; mi < 4; mi++)
#pragma unroll
                for (int ni = 0; ni < 4; ni++)
                    mma16816(acc[mi][ni], afr[mi], bfr[ni]);
            // product 3: Al @ Bh (reuse bfr) — skipped where output feeds only sigmoids
            if (np == 3) {
#pragma unroll
                for (int mi = 0; mi < 4; mi++) {
                    const int r = mbase + mi*16 + (lane & 15);
                    ldmA(afr[mi], aL + (r*PITCH + chA)*2);
                }
#pragma unroll
                for (int mi = 0; mi < 4; mi++)
#pragma unroll
                    for (int ni = 0; ni < 4; ni++)
                        mma16816(acc[mi][ni], afr[mi], bfr[ni]);
            }
        }
        __syncthreads();
    }

    // ---------------- epilogue ----------------
#pragma unroll
    for (int mi = 0; mi < 4; mi++) {
#pragma unroll
        for (int h2 = 0; h2 < 2; h2++) {
            const int rg = m0 + mbase + mi*16 + (lane >> 2) + h2*8;
#pragma unroll
            for (int ni = 0; ni < 4; ni++) {
                const int cg = n0 + nbase + ni*8 + (lane & 3)*2;
                const float v0 = acc[mi][ni][h2*2 + 0];
                const float v1 = acc[mi][ni][h2*2 + 1];
                if (g.mode == 0) {
                    const int s = rg >> 10, n = rg & 1023;
                    const int b = cg / g.fCnt;
                    const int f = g.fLo + (cg - b * g.fCnt);
                    const size_t base = (size_t)(n*64 + b) * g.k5 + (size_t)(s+1) * g.fp + f;
                    const __half h0 = __float2half_rn(v0), h1 = __float2half_rn(v1);
                    __half2 hh; hh.x = h0; hh.y = h1;
                    __half2 ll;
                    ll.x = __float2half_rn(v0 - __half2float(h0));
                    ll.y = __float2half_rn(v1 - __half2float(h1));
                    *(__half2*)(g_Ah + base) = hh;
                    *(__half2*)(g_Al + base) = ll;
                } else if (g.mode == 1) {
                    float2 o;
                    o.x = 1.f/(1.f + expf(-(v0 + g.bias[cg+0])));
                    o.y = 1.f/(1.f + expf(-(v1 + g.bias[cg+1])));
                    *(float2*)(g.gate + (size_t)rg*256 + cg) = o;
                } else {
                    const float2 u = *(const float2*)(g.gate + (size_t)rg*256 + 128 + cg);
                    const float2 so = *(const float2*)(g.state + (size_t)rg*128 + cg);
                    float2 o;
                    o.x = u.x*so.x + (1.f-u.x)*tanhf(v0 + g.bias[cg+0]);
                    o.y = u.y*so.y + (1.f-u.y)*tanhf(v1 + g.bias[cg+1]);
                    *(float2*)(g.state + (size_t)rg*128 + cg) = o;
                }
            }
        }
    }
}

// ---------------- fp32 SGEMM for prologue: C = 2 * A @ A (1024^3) ----------------
__global__ __launch_bounds__(256)
void sgemm_sq(const float* __restrict__ A, float* __restrict__ C)
{
    __shared__ float As[2][8][128];
    __shared__ float Bs[2][8][128];
    const int tid = threadIdx.x;
    const int m0 = blockIdx.y * 128, n0 = blockIdx.x * 128;
    const int arow = tid >> 1, acol = (tid & 1) << 2;
    const int brow = tid >> 5, bcol = (tid & 31) << 2;
    const float* Ap = A + (size_t)(m0 + arow) * NN + acol;
    const float* Bp = A + (size_t)brow * NN + n0 + bcol;
    const int tx = tid & 15, ty = tid >> 4;
    float acc[8][8];
#pragma unroll
    for (int i = 0; i < 8; i++)
#pragma unroll
        for (int j = 0; j < 8; j++) acc[i][j] = 0.f;
    float4 a4 = *(const float4*)Ap, b4 = *(const float4*)Bp;
    As[0][acol+0][arow]=a4.x; As[0][acol+1][arow]=a4.y; As[0][acol+2][arow]=a4.z; As[0][acol+3][arow]=a4.w;
    *(float4*)(&Bs[0][brow][bcol]) = b4;
    __syncthreads();
    for (int it = 0; it < 128; ++it) {
        const int buf = it & 1;
        if (it + 1 < 128) {
            const int k0 = (it + 1) << 3;
            a4 = *(const float4*)(Ap + k0);
            b4 = *(const float4*)(Bp + (size_t)k0 * NN);
        }
#pragma unroll
        for (int kk = 0; kk < 8; ++kk) {
            float ar[8], br[8];
            *(float4*)&ar[0] = *(const float4*)&As[buf][kk][ty*8];
            *(float4*)&ar[4] = *(const float4*)&As[buf][kk][ty*8+4];
            *(float4*)&br[0] = *(const float4*)&Bs[buf][kk][tx*8];
            *(float4*)&br[4] = *(const float4*)&Bs[buf][kk][tx*8+4];
#pragma unroll
            for (int i = 0; i < 8; i++)
#pragma unroll
                for (int j = 0; j < 8; j++) acc[i][j] = fmaf(ar[i], br[j], acc[i][j]);
        }
        if (it + 1 < 128) {
            const int nb2 = buf ^ 1;
            As[nb2][acol+0][arow]=a4.x; As[nb2][acol+1][arow]=a4.y; As[nb2][acol+2][arow]=a4.z; As[nb2][acol+3][arow]=a4.w;
            *(float4*)(&Bs[nb2][brow][bcol]) = b4;
            __syncthreads();
        }
    }
#pragma unroll
    for (int i = 0; i < 8; i++) {
        float* Cp = C + (size_t)(m0 + ty*8 + i) * NN + n0 + tx*8;
#pragma unroll
        for (int j = 0; j < 8; j++) Cp[j] = 2.f * acc[i][j];
    }
}

// ---------------- builders ----------------
// layer0 feature order: [s(128), inp(2), pad(30)]
__device__ __forceinline__ float xval0(const float* __restrict__ inp, int n, int b, int f, int reset){
    if (f < 128) {
        float s = g_s0[((size_t)n*64 + b)*HH + f];
        if (reset) s *= g_gate[((size_t)n*64 + b)*256 + f];
        return s;
    }
    if (f < 130) return inp[((size_t)b*NN + n)*2 + (f - 128)];
    return 0.f;
}
// layer1 feature order: [s0(128), s1(128)]
__device__ __forceinline__ float xval1(int n, int b, int f, int reset){
    if (f < HH) return g_s0[((size_t)n*64 + b)*HH + f];
    const int j = f - HH;
    float s = g_s1[((size_t)n*64 + b)*HH + j];
    if (reset) s *= g_gate[((size_t)n*64 + b)*256 + j];
    return s;
}

// Fused: writes A cols [fLo, fLo+fA) AND Xt rows (b*fCnt + j)*NN + n for j < fCnt
__global__ void build_ax(const float* __restrict__ inp, int layer, int reset,
                         int fLo, int fCnt, int fA, int k5){
    __shared__ float t[32][33];
    const int b = blockIdx.z, j0 = blockIdx.y*32, nt = blockIdx.x*32;
    const int tx = threadIdx.x, ty = threadIdx.y;
#pragma unroll
    for (int k = 0; k < 4; k++) {
        const int n = nt + ty + 8*k, f = fLo + j0 + tx;
        const float v = layer ? xval1(n, b, f, reset) : xval0(inp, n, b, f, reset);
        t[ty + 8*k][tx] = v;
        if (j0 + tx < fA) {
            __half h = __float2half_rn(v);
            const size_t ao = (size_t)(n*64 + b) * k5 + f;
            g_Ah[ao] = h;
            g_Al[ao] = __float2half_rn(v - __half2float(h));
        }
    }
    __syncthreads();
#pragma unroll
    for (int k = 0; k < 4; k++) {
        const int j = j0 + ty + 8*k, n = nt + tx;
        if (j < fCnt) {
            const float v = t[tx][ty + 8*k];
            __half h = __float2half_rn(v);
            const size_t o = ((size_t)b*fCnt + j)*NN + n;
            g_Xth[o] = h;
            g_Xtl[o] = __float2half_rn(v - __half2float(h));
        }
    }
}

__global__ void split_G(const float* __restrict__ sup){
    size_t i = (size_t)blockIdx.x * blockDim.x + threadIdx.x;
    if (i >= (size_t)4096*NN) return;
    const int row = (int)(i >> 10), col = (int)(i & 1023);
    const int slice = row >> 10, n = row & 1023;
    float v;
    if (slice == 0)      v = sup[(size_t)n*NN + col];
    else if (slice == 1) v = g_sq[(size_t)n*NN + col];
    else if (slice == 2) v = sup[(size_t)NN*NN + (size_t)n*NN + col];
    else                 v = g_sq[(size_t)NN*NN + (size_t)n*NN + col];
    __half h = __float2half_rn(v);
    g_Gh[i] = h;
    g_Gl[i] = __float2half_rn(v - __half2float(h));
}

// swapInp: layer0 reorder — W row for new f: f<128 -> orig 2+f; f in [128,130) -> orig f-128; else 0
__global__ void build_wt(__half* __restrict__ Wh, __half* __restrict__ Wl,
                         const float* __restrict__ src, int O, int F, int fp, int swapInp){
    const int k5 = 5*fp;
    int i = blockIdx.x * blockDim.x + threadIdx.x;
    if (i >= O*k5) return;
    const int o = i / k5, k = i - o*k5;
    const int t = k / fp, f = k - t*fp;
    int fo = f;
    if (swapInp) fo = (f < 128) ? (f + 2) : ((f < 130) ? (f - 128) : F);
    float v = 0.f;
    if (fo < F) {
        #define WSK(s,kx) src[((((size_t)(s))*3 + (kx))*F + fo)*O + o]
        switch (t) {
            case 0: v = WSK(0,0)+WSK(1,0)-WSK(0,2)-WSK(1,2); break;
            case 1: v = WSK(0,1); break;
            case 2: v = WSK(0,2); break;
            case 3: v = WSK(1,1); break;
            case 4: v = WSK(1,2); break;
        }
        #undef WSK
    }
    __half h = __float2half_rn(v);
    Wh[i] = h;
    Wl[i] = __float2half_rn(v - __half2float(h));
}

__global__ void write_out(float* __restrict__ out){
    const int nb = blockIdx.x, h = threadIdx.x;
    const int n = nb >> 6, b = nb & 63;
    out[(((size_t)0*BB + b)*NN + n)*HH + h] = g_s0[(size_t)nb*HH + h];
    out[(((size_t)1*BB + b)*NN + n)*HH + h] = g_s1[(size_t)nb*HH + h];
}

// ---------------- host ----------------
static void run_gemm(dim3 grid, const __half* Ah, const __half* Al,
                     const __half* Bh, const __half* Bl,
                     int lda, int ldb, int nch, int mode, int fp, int k5,
                     int fLo, int fCnt, int nprod, int trimOdd,
                     const float* bias, float* gate, float* state)
{
    GArgs g{Ah,Al,Bh,Bl,lda,ldb,nch,mode,fp,k5,fLo,fCnt,nprod,trimOdd,bias,gate,state};
    hgemm<<<grid, 256, SMEM_SZ>>>(g);
}

extern "C" void kernel_launch(void* const* d_in, const int* in_sizes, int n_in,
                              void* d_out, int out_size)
{
    const float* inputs = (const float*)d_in[0];
    const float* sup    = (const float*)d_in[1];
    const float* ruW0 = (const float*)d_in[2];
    const float* rub0 = (const float*)d_in[3];
    const float* hW0  = (const float*)d_in[4];
    const float* hb0  = (const float*)d_in[5];
    const float* ruW1 = (const float*)d_in[6];
    const float* rub1 = (const float*)d_in[7];
    const float* hW1  = (const float*)d_in[8];
    const float* hb1  = (const float*)d_in[9];
    float* out = (float*)d_out;

    cudaFuncSetAttribute(hgemm, cudaFuncAttributeMaxDynamicSharedMemorySize, SMEM_SZ);

    float *SQ, *S0, *S1, *GATE;
    __half *Ah, *Al, *Xth, *Xtl, *Gh, *Gl;
    __half *Wg0h,*Wg0l,*Wc0h,*Wc0l,*Wg1h,*Wg1l,*Wc1h,*Wc1l;
    cudaGetSymbolAddress((void**)&SQ, g_sq);
    cudaGetSymbolAddress((void**)&S0, g_s0);
    cudaGetSymbolAddress((void**)&S1, g_s1);
    cudaGetSymbolAddress((void**)&GATE, g_gate);
    cudaGetSymbolAddress((void**)&Ah, g_Ah);
    cudaGetSymbolAddress((void**)&Al, g_Al);
    cudaGetSymbolAddress((void**)&Xth, g_Xth);
    cudaGetSymbolAddress((void**)&Xtl, g_Xtl);
    cudaGetSymbolAddress((void**)&Gh, g_Gh);
    cudaGetSymbolAddress((void**)&Gl, g_Gl);
    cudaGetSymbolAddress((void**)&Wg0h, g_Wg0h); cudaGetSymbolAddress((void**)&Wg0l, g_Wg0l);
    cudaGetSymbolAddress((void**)&Wc0h, g_Wc0h); cudaGetSymbolAddress((void**)&Wc0l, g_Wc0l);
    cudaGetSymbolAddress((void**)&Wg1h, g_Wg1h); cudaGetSymbolAddress((void**)&Wg1l, g_Wg1l);
    cudaGetSymbolAddress((void**)&Wc1h, g_Wc1h); cudaGetSymbolAddress((void**)&Wc1l, g_Wc1l);

    // prologue
    sgemm_sq<<<dim3(8,8), 256>>>(sup, SQ);
    sgemm_sq<<<dim3(8,8), 256>>>(sup + (size_t)NN*NN, SQ + (size_t)NN*NN);
    split_G<<<(4096*1024)/256, 256>>>(sup);
    build_wt<<<(256*K50+255)/256, 256>>>(Wg0h, Wg0l, ruW0, 256, F0R, FP0, 1);
    build_wt<<<(128*K50+255)/256, 256>>>(Wc0h, Wc0l, hW0, 128, F0R, FP0, 1);
    build_wt<<<(256*K51+255)/256, 256>>>(Wg1h, Wg1l, ruW1, 256, FP1, FP1, 0);
    build_wt<<<(128*K51+255)/256, 256>>>(Wc1h, Wc1l, hW1, 128, FP1, FP1, 0);
    cudaMemsetAsync(S0, 0, (size_t)NB*HH*4);
    cudaMemsetAsync(S1, 0, (size_t)NB*HH*4);

    const dim3 gg0(65, 32);             // layer0 gate graph: 64*130/128 = 65 col blocks
    const dim3 gg1(BF1/128, 32);        // (128, 32) layer1 gate graph
    const dim3 gcand(64, 32);           // candidate graph (128 feats x 64 batch)
    const dim3 wgate(2, 512), wcand(1, 512);
    const dim3 bxt(32, 8);

    for (int t = 0; t < 12; ++t) {
        const float* inp = inputs + (size_t)t * BB * NN * 2;
        // ---- layer 0 gate: Xt over 130 real features (pads dropped); trimmed graph ----
        build_ax<<<dim3(32, 5, BB), bxt>>>(inp, 0, 0, 0, 130, FP0, K50);
        run_gemm(gg0, Gh, Gl, Xth, Xtl, NN, NN, 32, 0, FP0, K50, 0, 130, 2, 0, 0, 0, 0);
        run_gemm(wgate, Ah, Al, Wg0h, Wg0l, K50, K50, 25, 1, FP0, K50, 0, 0, 2, 0, rub0, GATE, 0);
        // ---- layer 0 candidate: only s-features change; graph trimmed, weight exact ----
        build_ax<<<dim3(32, 4, BB), bxt>>>(inp, 0, 1, 0, 128, 128, K50);
        run_gemm(gcand, Gh, Gl, Xth, Xtl, NN, NN, 32, 0, FP0, K50, 0, 128, 2, 0, 0, 0, 0);
        run_gemm(wcand, Ah, Al, Wc0h, Wc0l, K50, K50, 25, 2, FP0, K50, 0, 0, 3, 0, hb0, GATE, S0);
        // ---- layer 1 gate: even blocks (s0 Y cols, reused by cand weight) exact;
        //      odd blocks (s1 Y cols, gates only) trimmed ----
        build_ax<<<dim3(32, FP1/32, BB), bxt>>>(inp, 1, 0, 0, FP1, FP1, K51);
        run_gemm(gg1, Gh, Gl, Xth, Xtl, NN, NN, 32, 0, FP1, K51, 0, FP1, 3, 1, 0, 0, 0);
        run_gemm(wgate, Ah, Al, Wg1h, Wg1l, K51, K51, 40, 1, FP1, K51, 0, 0, 2, 0, rub1, GATE, 0);
        // ---- layer 1 candidate: only s1-features change; graph trimmed, weight exact ----
        build_ax<<<dim3(32, 4, BB), bxt>>>(inp, 1, 1, 128, 128, 128, K51);
        run_gemm(gcand, Gh, Gl, Xth, Xtl, NN, NN, 32, 0, FP1, K51, 128, 128, 2, 0, 0, 0, 0);
        run_gemm(wcand, Ah, Al, Wc1h, Wc1l, K51, K51, 40, 2, FP1, K51, 0, 0, 3, 0, hb1, GATE, S1);
    }
    write_out<<<NB, 128>>>(out);
}

// round 17
// speedup vs baseline: 1.4894x; 1.0515x over previous
#include <cuda_runtime.h>
#include <cuda_fp16.h>
#include <math.h>
#include <stdint.h>

#define NN 1024
#define BB 64
#define NB 65536
#define HH 128
#define F0R 130
#define FP0 160                  // layer0 padded features, [s(128), inp(2), 0...]
#define FP1 256
#define BF1 (BB*FP1)             // 16384
#define K50 (5*FP0)              // 800
#define K51 (5*FP1)              // 1280
#define PITCH 40                 // halves per smem row (80B, 16B-aligned, conflict-free)
#define TSH (128*PITCH)
#define SMEM_SZ (2*4*TSH*2)      // 81920

// ---------------- static device scratch ----------------
__device__ __align__(128) __half g_Ah[(size_t)NB*K51];
__device__ __align__(128) __half g_Al[(size_t)NB*K51];
__device__ __align__(128) __half g_Xth[(size_t)BF1*NN];
__device__ __align__(128) __half g_Xtl[(size_t)BF1*NN];
__device__ __align__(128) __half g_Gh[(size_t)4096*NN];
__device__ __align__(128) __half g_Gl[(size_t)4096*NN];
__device__ __align__(128) float  g_sq[(size_t)2*NN*NN];
__device__ __align__(128) __half g_Wg0h[256*K50], g_Wg0l[256*K50];
__device__ __align__(128) __half g_Wc0h[128*K50], g_Wc0l[128*K50];
__device__ __align__(128) __half g_Wg1h[256*K51], g_Wg1l[256*K51];
__device__ __align__(128) __half g_Wc1h[128*K51], g_Wc1l[128*K51];
__device__ __align__(128) float  g_gate[(size_t)NB*256];
__device__ __align__(128) float  g_s0[(size_t)NB*HH];
__device__ __align__(128) float  g_s1[(size_t)NB*HH];

// ---------------- helpers ----------------
__device__ __forceinline__ uint32_t smem_u32(const void* p){
    uint32_t a; asm("{ .reg .u64 t; cvta.to.shared.u64 t, %1; cvt.u32.u64 %0, t; }":"=r"(a):"l"(p)); return a;
}
__device__ __forceinline__ void cp16(uint32_t d, const void* s){
    asm volatile("cp.async.cg.shared.global [%0], [%1], 16;\n"::"r"(d),"l"(s):"memory");
}
__device__ __forceinline__ void ldmA(uint32_t* a, uint32_t addr){
    asm volatile("ldmatrix.sync.aligned.m8n8.x4.shared.b16 {%0,%1,%2,%3}, [%4];"
        : "=r"(a[0]),"=r"(a[1]),"=r"(a[2]),"=r"(a[3]) : "r"(addr));
}
__device__ __forceinline__ void ldmB(uint32_t* b, uint32_t addr){
    asm volatile("ldmatrix.sync.aligned.m8n8.x2.shared.b16 {%0,%1}, [%2];"
        : "=r"(b[0]),"=r"(b[1]) : "r"(addr));
}
__device__ __forceinline__ void mma16816(float* d, const uint32_t* a, const uint32_t* b){
    asm volatile("mma.sync.aligned.m16n8k16.row.col.f32.f16.f16.f32 "
        "{%0,%1,%2,%3},{%4,%5,%6,%7},{%8,%9},{%0,%1,%2,%3};"
        : "+f"(d[0]),"+f"(d[1]),"+f"(d[2]),"+f"(d[3])
        : "r"(a[0]),"r"(a[1]),"r"(a[2]),"r"(a[3]),"r"(b[0]),"r"(b[1]));
}

// ---------------- fp16-split HGEMM: quad-tile, 1-3 products per K-chunk ----------------
// np==3: Ah@Bl + Ah@Bh + Al@Bh ; np==2: Ah@Bl + Ah@Bh ; np==1: Ah@Bh only.
// trimOdd: blocks with odd blockIdx.x use nprod=2 (their output columns feed only sigmoid gates)
// fill() loads only the tiles the active product set reads.
// mode 0: split-write Y into g_Ah/g_Al; B rows are (b*fCnt + j), feature f = fLo + j
// mode 1: gate[row*256+c] = sigmoid(v + bias[c])
// mode 2: state[row*128+c] = u*s + (1-u)*tanh(v + bias[c])
struct GArgs {
    const __half *Ah,*Al,*Bh,*Bl;
    int lda, ldb, nch, mode, fp, k5, fLo, fCnt, nprod, trimOdd;
    const float* bias; float* gate; float* state;
};

__global__ __launch_bounds__(256,2) void hgemm(GArgs g)
{
    extern __shared__ __align__(16) __half sm[];
    const int tid = threadIdx.x;
    const int wid = tid >> 5, lane = tid & 31;
    const int m0 = blockIdx.y * 128, n0 = blockIdx.x * 128;
    const int mbase = (wid >> 2) * 64, nbase = (wid & 3) * 32;
    const uint32_t smb = smem_u32(sm);
    const int np = (g.trimOdd && (blockIdx.x & 1)) ? 2 : g.nprod;

    float acc[4][4][4];
#pragma unroll
    for (int i = 0; i < 4; i++)
#pragma unroll
        for (int j = 0; j < 4; j++)
#pragma unroll
            for (int k = 0; k < 4; k++) acc[i][j][k] = 0.f;

    const int lr = tid >> 2;
    const int lc = (tid & 3) * 8;

    auto fill = [&](int c, int buf){
        const int k0 = c * 32;
        const __half* srcs[4] = {
            g.Ah + (size_t)m0 * g.lda + k0,
            g.Al + (size_t)m0 * g.lda + k0,
            g.Bh + (size_t)n0 * g.ldb + k0,
            g.Bl + (size_t)n0 * g.ldb + k0 };
        const int lds[4] = { g.lda, g.lda, g.ldb, g.ldb };
        const uint32_t base = smb + buf * 4*TSH*2;
#pragma unroll
        for (int t = 0; t < 4; t++) {
            if (t == 1 && np < 3) continue;    // Al tile: only product 3 reads it
            if (t == 3 && np < 2) continue;    // Bl tile: only product 1 reads it
            const uint32_t tb = base + t * TSH*2;
#pragma unroll
            for (int h = 0; h < 2; h++) {
                const int r = lr + h * 64;
                cp16(tb + (r*PITCH + lc)*2, srcs[t] + (size_t)r * lds[t] + lc);
            }
        }
        asm volatile("cp.async.commit_group;\n":::"memory");
    };

    fill(0, 0);
    for (int c = 0; c < g.nch; c++) {
        const int buf = c & 1;
        if (c + 1 < g.nch) {
            fill(c + 1, buf ^ 1);
            asm volatile("cp.async.wait_group 1;\n":::"memory");
        } else {
            asm volatile("cp.async.wait_group 0;\n":::"memory");
        }
        __syncthreads();
        const uint32_t base = smb + buf * 4*TSH*2;
        const uint32_t aH = base, aL = base + TSH*2;
        const uint32_t bH = base + 2*TSH*2, bL = base + 3*TSH*2;
#pragma unroll
        for (int ks = 0; ks < 2; ks++) {
            const int chA = ks*16 + (lane >> 4) * 8;
            const int lB = lane & 15;
            const int chB = ks*16 + (lB >> 3) * 8;
            uint32_t afr[4][4], bfr[4][2];
            // A head fragments (used by products 1 and 2)
#pragma unroll
            for (int mi = 0; mi < 4; mi++) {
                const int r = mbase + mi*16 + (lane & 15);
                ldmA(afr[mi], aH + (r*PITCH + chA)*2);
            }
            // product 1: Ah @ Bl (skipped when np==1)
            if (np >= 2) {
#pragma unroll
                for (int ni = 0; ni < 4; ni++) {
                    const int r = nbase + ni*8 + (lB & 7);
                    ldmB(bfr[ni], bL + (r*PITCH + chB)*2);
                }
#pragma unroll
                for (int mi = 0; mi < 4; mi++)
#pragma unroll
                    for (int ni = 0; ni < 4; ni++)
                        mma16816(acc[mi][ni], afr[mi], bfr[ni]);
            }
            // product 2: Ah @ Bh (reuse afr)
#pragma unroll
            for (int ni = 0; ni < 4; ni++) {
                const int r = nbase + ni*8 + (lB & 7);
                ldmB(bfr[ni], bH + (r*PITCH + chB)*2);
            }
#pragma unroll
            for (int mi = 0; mi < 4; mi++)
#pragma unroll
                for (int ni = 0; ni < 4; ni++)
                    mma16816(acc[mi][ni], afr[mi], bfr[ni]);
            // product 3: Al @ Bh (reuse bfr) — exact paths only
            if (np == 3) {
#pragma unroll
                for (int mi = 0; mi < 4; mi++) {
                    const int r = mbase + mi*16 + (lane & 15);
                    ldmA(afr[mi], aL + (r*PITCH + chA)*2);
                }
#pragma unroll
                for (int mi = 0; mi < 4; mi++)
#pragma unroll
                    for (int ni = 0; ni < 4; ni++)
                        mma16816(acc[mi][ni], afr[mi], bfr[ni]);
            }
        }
        __syncthreads();
    }

    // ---------------- epilogue ----------------
#pragma unroll
    for (int mi = 0; mi < 4; mi++) {
#pragma unroll
        for (int h2 = 0; h2 < 2; h2++) {
            const int rg = m0 + mbase + mi*16 + (lane >> 2) + h2*8;
#pragma unroll
            for (int ni = 0; ni < 4; ni++) {
                const int cg = n0 + nbase + ni*8 + (lane & 3)*2;
                const float v0 = acc[mi][ni][h2*2 + 0];
                const float v1 = acc[mi][ni][h2*2 + 1];
                if (g.mode == 0) {
                    const int s = rg >> 10, n = rg & 1023;
                    const int b = cg / g.fCnt;
                    const int f = g.fLo + (cg - b * g.fCnt);
                    const size_t base = (size_t)(n*64 + b) * g.k5 + (size_t)(s+1) * g.fp + f;
                    const __half h0 = __float2half_rn(v0), h1 = __float2half_rn(v1);
                    __half2 hh; hh.x = h0; hh.y = h1;
                    __half2 ll;
                    ll.x = __float2half_rn(v0 - __half2float(h0));
                    ll.y = __float2half_rn(v1 - __half2float(h1));
                    *(__half2*)(g_Ah + base) = hh;
                    *(__half2*)(g_Al + base) = ll;
                } else if (g.mode == 1) {
                    float2 o;
                    o.x = 1.f/(1.f + expf(-(v0 + g.bias[cg+0])));
                    o.y = 1.f/(1.f + expf(-(v1 + g.bias[cg+1])));
                    *(float2*)(g.gate + (size_t)rg*256 + cg) = o;
                } else {
                    const float2 u = *(const float2*)(g.gate + (size_t)rg*256 + 128 + cg);
                    const float2 so = *(const float2*)(g.state + (size_t)rg*128 + cg);
                    float2 o;
                    o.x = u.x*so.x + (1.f-u.x)*tanhf(v0 + g.bias[cg+0]);
                    o.y = u.y*so.y + (1.f-u.y)*tanhf(v1 + g.bias[cg+1]);
                    *(float2*)(g.state + (size_t)rg*128 + cg) = o;
                }
            }
        }
    }
}

// ---------------- fp32 SGEMM for prologue: C = 2 * A @ A (1024^3) ----------------
__global__ __launch_bounds__(256)
void sgemm_sq(const float* __restrict__ A, float* __restrict__ C)
{
    __shared__ float As[2][8][128];
    __shared__ float Bs[2][8][128];
    const int tid = threadIdx.x;
    const int m0 = blockIdx.y * 128, n0 = blockIdx.x * 128;
    const int arow = tid >> 1, acol = (tid & 1) << 2;
    const int brow = tid >> 5, bcol = (tid & 31) << 2;
    const float* Ap = A + (size_t)(m0 + arow) * NN + acol;
    const float* Bp = A + (size_t)brow * NN + n0 + bcol;
    const int tx = tid & 15, ty = tid >> 4;
    float acc[8][8];
#pragma unroll
    for (int i = 0; i < 8; i++)
#pragma unroll
        for (int j = 0; j < 8; j++) acc[i][j] = 0.f;
    float4 a4 = *(const float4*)Ap, b4 = *(const float4*)Bp;
    As[0][acol+0][arow]=a4.x; As[0][acol+1][arow]=a4.y; As[0][acol+2][arow]=a4.z; As[0][acol+3][arow]=a4.w;
    *(float4*)(&Bs[0][brow][bcol]) = b4;
    __syncthreads();
    for (int it = 0; it < 128; ++it) {
        const int buf = it & 1;
        if (it + 1 < 128) {
            const int k0 = (it + 1) << 3;
            a4 = *(const float4*)(Ap + k0);
            b4 = *(const float4*)(Bp + (size_t)k0 * NN);
        }
#pragma unroll
        for (int kk = 0; kk < 8; ++kk) {
            float ar[8], br[8];
            *(float4*)&ar[0] = *(const float4*)&As[buf][kk][ty*8];
            *(float4*)&ar[4] = *(const float4*)&As[buf][kk][ty*8+4];
            *(float4*)&br[0] = *(const float4*)&Bs[buf][kk][tx*8];
            *(float4*)&br[4] = *(const float4*)&Bs[buf][kk][tx*8+4];
#pragma unroll
            for (int i = 0; i < 8; i++)
#pragma unroll
                for (int j = 0; j < 8; j++) acc[i][j] = fmaf(ar[i], br[j], acc[i][j]);
        }
        if (it + 1 < 128) {
            const int nb2 = buf ^ 1;
            As[nb2][acol+0][arow]=a4.x; As[nb2][acol+1][arow]=a4.y; As[nb2][acol+2][arow]=a4.z; As[nb2][acol+3][arow]=a4.w;
            *(float4*)(&Bs[nb2][brow][bcol]) = b4;
            __syncthreads();
        }
    }
#pragma unroll
    for (int i = 0; i < 8; i++) {
        float* Cp = C + (size_t)(m0 + ty*8 + i) * NN + n0 + tx*8;
#pragma unroll
        for (int j = 0; j < 8; j++) Cp[j] = 2.f * acc[i][j];
    }
}

// ---------------- builders ----------------
// layer0 feature order: [s(128), inp(2), pad(30)]
__device__ __forceinline__ float xval0(const float* __restrict__ inp, int n, int b, int f, int reset){
    if (f < 128) {
        float s = g_s0[((size_t)n*64 + b)*HH + f];
        if (reset) s *= g_gate[((size_t)n*64 + b)*256 + f];
        return s;
    }
    if (f < 130) return inp[((size_t)b*NN + n)*2 + (f - 128)];
    return 0.f;
}
// layer1 feature order: [s0(128), s1(128)]
__device__ __forceinline__ float xval1(int n, int b, int f, int reset){
    if (f < HH) return g_s0[((size_t)n*64 + b)*HH + f];
    const int j = f - HH;
    float s = g_s1[((size_t)n*64 + b)*HH + j];
    if (reset) s *= g_gate[((size_t)n*64 + b)*256 + j];
    return s;
}

// Fused: writes A cols [fLo, fLo+fA) AND Xt rows (b*fCnt + j)*NN + n for j < fCnt
__global__ void build_ax(const float* __restrict__ inp, int layer, int reset,
                         int fLo, int fCnt, int fA, int k5){
    __shared__ float t[32][33];
    const int b = blockIdx.z, j0 = blockIdx.y*32, nt = blockIdx.x*32;
    const int tx = threadIdx.x, ty = threadIdx.y;
#pragma unroll
    for (int k = 0; k < 4; k++) {
        const int n = nt + ty + 8*k, f = fLo + j0 + tx;
        const float v = layer ? xval1(n, b, f, reset) : xval0(inp, n, b, f, reset);
        t[ty + 8*k][tx] = v;
        if (j0 + tx < fA) {
            __half h = __float2half_rn(v);
            const size_t ao = (size_t)(n*64 + b) * k5 + f;
            g_Ah[ao] = h;
            g_Al[ao] = __float2half_rn(v - __half2float(h));
        }
    }
    __syncthreads();
#pragma unroll
    for (int k = 0; k < 4; k++) {
        const int j = j0 + ty + 8*k, n = nt + tx;
        if (j < fCnt) {
            const float v = t[tx][ty + 8*k];
            __half h = __float2half_rn(v);
            const size_t o = ((size_t)b*fCnt + j)*NN + n;
            g_Xth[o] = h;
            g_Xtl[o] = __float2half_rn(v - __half2float(h));
        }
    }
}

__global__ void split_G(const float* __restrict__ sup){
    size_t i = (size_t)blockIdx.x * blockDim.x + threadIdx.x;
    if (i >= (size_t)4096*NN) return;
    const int row = (int)(i >> 10), col = (int)(i & 1023);
    const int slice = row >> 10, n = row & 1023;
    float v;
    if (slice == 0)      v = sup[(size_t)n*NN + col];
    else if (slice == 1) v = g_sq[(size_t)n*NN + col];
    else if (slice == 2) v = sup[(size_t)NN*NN + (size_t)n*NN + col];
    else                 v = g_sq[(size_t)NN*NN + (size_t)n*NN + col];
    __half h = __float2half_rn(v);
    g_Gh[i] = h;
    g_Gl[i] = __float2half_rn(v - __half2float(h));
}

// swapInp: layer0 reorder — W row for new f: f<128 -> orig 2+f; f in [128,130) -> orig f-128; else 0
__global__ void build_wt(__half* __restrict__ Wh, __half* __restrict__ Wl,
                         const float* __restrict__ src, int O, int F, int fp, int swapInp){
    const int k5 = 5*fp;
    int i = blockIdx.x * blockDim.x + threadIdx.x;
    if (i >= O*k5) return;
    const int o = i / k5, k = i - o*k5;
    const int t = k / fp, f = k - t*fp;
    int fo = f;
    if (swapInp) fo = (f < 128) ? (f + 2) : ((f < 130) ? (f - 128) : F);
    float v = 0.f;
    if (fo < F) {
        #define WSK(s,kx) src[((((size_t)(s))*3 + (kx))*F + fo)*O + o]
        switch (t) {
            case 0: v = WSK(0,0)+WSK(1,0)-WSK(0,2)-WSK(1,2); break;
            case 1: v = WSK(0,1); break;
            case 2: v = WSK(0,2); break;
            case 3: v = WSK(1,1); break;
            case 4: v = WSK(1,2); break;
        }
        #undef WSK
    }
    __half h = __float2half_rn(v);
    Wh[i] = h;
    Wl[i] = __float2half_rn(v - __half2float(h));
}

__global__ void write_out(float* __restrict__ out){
    const int nb = blockIdx.x, h = threadIdx.x;
    const int n = nb >> 6, b = nb & 63;
    out[(((size_t)0*BB + b)*NN + n)*HH + h] = g_s0[(size_t)nb*HH + h];
    out[(((size_t)1*BB + b)*NN + n)*HH + h] = g_s1[(size_t)nb*HH + h];
}

// ---------------- host ----------------
static void run_gemm(dim3 grid, const __half* Ah, const __half* Al,
                     const __half* Bh, const __half* Bl,
                     int lda, int ldb, int nch, int mode, int fp, int k5,
                     int fLo, int fCnt, int nprod, int trimOdd,
                     const float* bias, float* gate, float* state)
{
    GArgs g{Ah,Al,Bh,Bl,lda,ldb,nch,mode,fp,k5,fLo,fCnt,nprod,trimOdd,bias,gate,state};
    hgemm<<<grid, 256, SMEM_SZ>>>(g);
}

extern "C" void kernel_launch(void* const* d_in, const int* in_sizes, int n_in,
                              void* d_out, int out_size)
{
    const float* inputs = (const float*)d_in[0];
    const float* sup    = (const float*)d_in[1];
    const float* ruW0 = (const float*)d_in[2];
    const float* rub0 = (const float*)d_in[3];
    const float* hW0  = (const float*)d_in[4];
    const float* hb0  = (const float*)d_in[5];
    const float* ruW1 = (const float*)d_in[6];
    const float* rub1 = (const float*)d_in[7];
    const float* hW1  = (const float*)d_in[8];
    const float* hb1  = (const float*)d_in[9];
    float* out = (float*)d_out;

    cudaFuncSetAttribute(hgemm, cudaFuncAttributeMaxDynamicSharedMemorySize, SMEM_SZ);

    float *SQ, *S0, *S1, *GATE;
    __half *Ah, *Al, *Xth, *Xtl, *Gh, *Gl;
    __half *Wg0h,*Wg0l,*Wc0h,*Wc0l,*Wg1h,*Wg1l,*Wc1h,*Wc1l;
    cudaGetSymbolAddress((void**)&SQ, g_sq);
    cudaGetSymbolAddress((void**)&S0, g_s0);
    cudaGetSymbolAddress((void**)&S1, g_s1);
    cudaGetSymbolAddress((void**)&GATE, g_gate);
    cudaGetSymbolAddress((void**)&Ah, g_Ah);
    cudaGetSymbolAddress((void**)&Al, g_Al);
    cudaGetSymbolAddress((void**)&Xth, g_Xth);
    cudaGetSymbolAddress((void**)&Xtl, g_Xtl);
    cudaGetSymbolAddress((void**)&Gh, g_Gh);
    cudaGetSymbolAddress((void**)&Gl, g_Gl);
    cudaGetSymbolAddress((void**)&Wg0h, g_Wg0h); cudaGetSymbolAddress((void**)&Wg0l, g_Wg0l);
    cudaGetSymbolAddress((void**)&Wc0h, g_Wc0h); cudaGetSymbolAddress((void**)&Wc0l, g_Wc0l);
    cudaGetSymbolAddress((void**)&Wg1h, g_Wg1h); cudaGetSymbolAddress((void**)&Wg1l, g_Wg1l);
    cudaGetSymbolAddress((void**)&Wc1h, g_Wc1h); cudaGetSymbolAddress((void**)&Wc1l, g_Wc1l);

    // prologue
    sgemm_sq<<<dim3(8,8), 256>>>(sup, SQ);
    sgemm_sq<<<dim3(8,8), 256>>>(sup + (size_t)NN*NN, SQ + (size_t)NN*NN);
    split_G<<<(4096*1024)/256, 256>>>(sup);
    build_wt<<<(256*K50+255)/256, 256>>>(Wg0h, Wg0l, ruW0, 256, F0R, FP0, 1);
    build_wt<<<(128*K50+255)/256, 256>>>(Wc0h, Wc0l, hW0, 128, F0R, FP0, 1);
    build_wt<<<(256*K51+255)/256, 256>>>(Wg1h, Wg1l, ruW1, 256, FP1, FP1, 0);
    build_wt<<<(128*K51+255)/256, 256>>>(Wc1h, Wc1l, hW1, 128, FP1, FP1, 0);
    cudaMemsetAsync(S0, 0, (size_t)NB*HH*4);
    cudaMemsetAsync(S1, 0, (size_t)NB*HH*4);

    const dim3 gg0(65, 32);             // layer0 gate graph: 64*130/128 = 65 col blocks
    const dim3 gg1(BF1/128, 32);        // (128, 32) layer1 gate graph
    const dim3 gcand(64, 32);           // candidate graph (128 feats x 64 batch)
    const dim3 wgate(2, 512), wcand(1, 512);
    const dim3 bxt(32, 8);

    for (int t = 0; t < 12; ++t) {
        const float* inp = inputs + (size_t)t * BB * NN * 2;
        // ---- layer 0 gate: Xt over 130 real features; graph trimmed, weight single-product ----
        build_ax<<<dim3(32, 5, BB), bxt>>>(inp, 0, 0, 0, 130, FP0, K50);
        run_gemm(gg0, Gh, Gl, Xth, Xtl, NN, NN, 32, 0, FP0, K50, 0, 130, 2, 0, 0, 0, 0);
        run_gemm(wgate, Ah, Al, Wg0h, Wg0l, K50, K50, 25, 1, FP0, K50, 0, 0, 1, 0, rub0, GATE, 0);
        // ---- layer 0 candidate: only s-features change; graph trimmed, weight exact ----
        build_ax<<<dim3(32, 4, BB), bxt>>>(inp, 0, 1, 0, 128, 128, K50);
        run_gemm(gcand, Gh, Gl, Xth, Xtl, NN, NN, 32, 0, FP0, K50, 0, 128, 2, 0, 0, 0, 0);
        run_gemm(wcand, Ah, Al, Wc0h, Wc0l, K50, K50, 25, 2, FP0, K50, 0, 0, 3, 0, hb0, GATE, S0);
        // ---- layer 1 gate: even blocks (s0 Y cols, reused by cand weight) exact;
        //      odd blocks (s1 Y cols, gates only) trimmed; weight single-product ----
        build_ax<<<dim3(32, FP1/32, BB), bxt>>>(inp, 1, 0, 0, FP1, FP1, K51);
        run_gemm(gg1, Gh, Gl, Xth, Xtl, NN, NN, 32, 0, FP1, K51, 0, FP1, 3, 1, 0, 0, 0);
        run_gemm(wgate, Ah, Al, Wg1h, Wg1l, K51, K51, 40, 1, FP1, K51, 0, 0, 1, 0, rub1, GATE, 0);
        // ---- layer 1 candidate: only s1-features change; graph trimmed, weight exact ----
        build_ax<<<dim3(32, 4, BB), bxt>>>(inp, 1, 1, 128, 128, 128, K51);
        run_gemm(gcand, Gh, Gl, Xth, Xtl, NN, NN, 32, 0, FP1, K51, 128, 128, 2, 0, 0, 0, 0);
        run_gemm(wcand, Ah, Al, Wc1h, Wc1l, K51, K51, 40, 2, FP1, K51, 0, 0, 3, 0, hb1, GATE, S1);
    }
    write_out<<<NB, 128>>>(out);
}